// round 12
// baseline (speedup 1.0000x reference)
#include <cuda_runtime.h>
#include <math.h>

#define NTOK 401
#define NPT  400
#define DIMM 512
#define NHEAD 8
#define HDIM 64
#define QKV3 1536
#define CPBH 512
#define NPAIR (NTOK*NTOK)
#define TABN 4096
#define SROW 420
#define PI_F 3.14159265358979323846f
#define FLAG_RELU 1
#define FLAG_ADD  2
#define FLAG_RAW  4

// ---------------- scratch (alloc-free, __device__ globals) ----------------
__device__ float  g_h[NTOK*DIMM];          // residual stream
__device__ float  g_ln[NTOK*DIMM];         // layernorm output
__device__ float  g_qkv[NTOK*QKV3];        // fused qkv
__device__ float  g_ao[NTOK*DIMM];         // attention output (pre-proj)
__device__ float  g_part[4*NTOK*QKV3];     // split-K partials (9.9 MB)
__device__ float  g_angpos[NPAIR];         // table position per pair (both layers)
__device__ float  g_coords[NTOK*2];
__device__ float  g_table0[(TABN+4)*8];    // layer-1 bias table
__device__ float  g_table1[(TABN+4)*8];    // layer-2 bias table

// ---------------- small helpers ----------------
__device__ __forceinline__ float2 blockReduce2_256(float a, float b) {
    __shared__ float sa[8], sb[8];
    __syncthreads();
    #pragma unroll
    for (int o = 16; o > 0; o >>= 1) {
        a += __shfl_xor_sync(0xffffffffu, a, o);
        b += __shfl_xor_sync(0xffffffffu, b, o);
    }
    int w = threadIdx.x >> 5;
    if ((threadIdx.x & 31) == 0) { sa[w] = a; sb[w] = b; }
    __syncthreads();
    a = sa[0]+sa[1]+sa[2]+sa[3]+sa[4]+sa[5]+sa[6]+sa[7];
    b = sb[0]+sb[1]+sb[2]+sb[3]+sb[4]+sb[5]+sb[6]+sb[7];
    return make_float2(a, b);
}

// ---------------- setup: CLS row + coords (CLS coord = 0) ----------------
__global__ void setup_kernel(const float* __restrict__ cls,
                             const float* __restrict__ coords) {
    int t = blockIdx.x*blockDim.x + threadIdx.x;
    if (t < DIMM)  g_h[t] = cls[t];
    if (t < 2)     g_coords[t] = 0.f;
    if (t < NPT*2) g_coords[2+t] = coords[t];
}

// ---------------- per-pair angle table position ----------------
__global__ void angpos_kernel() {
    int p = blockIdx.x*blockDim.x + threadIdx.x;
    if (p >= NPAIR) return;
    int i = p / NTOK, j = p - i*NTOK;
    float pos;
    if (i == j) {
        pos = (float)(TABN + 1);           // diag: dir = (0,0) special row
    } else {
        float dx = g_coords[2*i]   - g_coords[2*j];
        float dy = g_coords[2*i+1] - g_coords[2*j+1];
        float th = atan2f(dy, dx);
        pos = (th + PI_F) * ((float)TABN / (2.0f*PI_F));
        pos = fminf(fmaxf(pos, 0.f), (float)TABN);
    }
    g_angpos[p] = pos;
}

// ---------------- build CPB bias tables (both layers, grid.y selects) ----
__global__ void __launch_bounds__(256) cpb_table_kernel(
        const float* __restrict__ w1a, const float* __restrict__ b1a,
        const float* __restrict__ w2a, const float* __restrict__ b2a,
        float* __restrict__ outa,
        const float* __restrict__ w1b, const float* __restrict__ b1b,
        const float* __restrict__ w2b, const float* __restrict__ b2b,
        float* __restrict__ outb) {
    const float* w1 = blockIdx.y ? w1b : w1a;
    const float* b1 = blockIdx.y ? b1b : b1a;
    const float* w2 = blockIdx.y ? w2b : w2a;
    const float* b2 = blockIdx.y ? b2b : b2a;
    float*      out = blockIdx.y ? outb : outa;

    __shared__ float swx[CPBH], swy[CPBH], sbb[CPBH];
    __shared__ __align__(16) float sw2[CPBH*8];
    __shared__ float sred[8][32][9];
    int t = threadIdx.x;
    for (int c = t; c < CPBH; c += 256) {
        swx[c] = w1[c]; swy[c] = w1[CPBH + c]; sbb[c] = b1[c];
    }
    for (int c = t; c < CPBH*2; c += 256)
        *(float4*)(sw2 + c*4) = *(const float4*)(w2 + c*4);
    __syncthreads();

    int e = t & 31;
    int w = t >> 5;
    int idx = blockIdx.x*32 + e;
    float ux = 0.f, uy = 0.f;
    if (idx <= TABN) {
        float th = -PI_F + (2.0f*PI_F) * ((float)idx / (float)TABN);
        sincosf(th, &uy, &ux);
    }
    float acc[8] = {0.f,0.f,0.f,0.f,0.f,0.f,0.f,0.f};
    int c0 = w << 6;
    #pragma unroll 8
    for (int cc = 0; cc < 64; cc++) {
        int c = c0 + cc;
        float hv = fmaf(ux, swx[c], fmaf(uy, swy[c], sbb[c]));
        hv = fmaxf(hv, 0.f);
        float4 wa = *(const float4*)(sw2 + (c<<3));
        float4 wb = *(const float4*)(sw2 + (c<<3) + 4);
        acc[0] = fmaf(hv, wa.x, acc[0]);
        acc[1] = fmaf(hv, wa.y, acc[1]);
        acc[2] = fmaf(hv, wa.z, acc[2]);
        acc[3] = fmaf(hv, wa.w, acc[3]);
        acc[4] = fmaf(hv, wb.x, acc[4]);
        acc[5] = fmaf(hv, wb.y, acc[5]);
        acc[6] = fmaf(hv, wb.z, acc[6]);
        acc[7] = fmaf(hv, wb.w, acc[7]);
    }
    #pragma unroll
    for (int k = 0; k < 8; k++) sred[w][e][k] = acc[k];
    __syncthreads();

    int re = t >> 3, rk = t & 7;
    float s = 0.f;
    #pragma unroll
    for (int ww = 0; ww < 8; ww++) s += sred[ww][re][rk];
    int ridx = blockIdx.x*32 + re;
    if (ridx <= TABN + 2) {
        float v = (ridx == TABN + 2) ? 0.f : s + b2[rk];
        out[(size_t)ridx*8 + rk] = v;
    }
}

// ---------------- 32x64-tile fp32 GEMM, 128 threads, 4x4/thread -----------
// CTA-level split-K via blockIdx.z; with FLAG_RAW partials to C + z*M*ldc.
__global__ void __launch_bounds__(128) gemm_kernel(
        const float* __restrict__ A, int lda,
        const float* __restrict__ B, int ldb,
        const float* __restrict__ bias,
        float* __restrict__ C, int ldc,
        int M, int N, int K, int flags) {
    __shared__ __align__(16) float As[2][16][36];
    __shared__ __align__(16) float Bs[2][16][68];
    int t  = threadIdx.x;
    int m0 = blockIdx.y << 5, n0 = blockIdx.x << 6;
    int zi = blockIdx.z;
    const float* Az = A + (size_t)zi*K;
    const float* Bz = B + (size_t)zi*K*ldb;
    float* Cz = C + (size_t)zi*M*ldc;
    int arow = t >> 2, acol = (t & 3) << 2;
    int brow = t >> 3, bcol = (t & 7) << 3;
    int tx = t & 15, ty = t >> 4;
    float acc[4][4] = {};

    bool aval = (m0 + arow) < M;
    const float* Aptr = Az + (size_t)(m0 + arow)*lda + acol;
    const float* Bptr = Bz + (size_t)brow*ldb + n0 + bcol;

    float4 ra  = aval ? *(const float4*)Aptr : make_float4(0.f,0.f,0.f,0.f);
    float4 rb0 = *(const float4*)Bptr;
    float4 rb1 = *(const float4*)(Bptr + 4);
    int buf = 0;
    As[0][acol  ][arow] = ra.x; As[0][acol+1][arow] = ra.y;
    As[0][acol+2][arow] = ra.z; As[0][acol+3][arow] = ra.w;
    *(float4*)&Bs[0][brow][bcol]   = rb0;
    *(float4*)&Bs[0][brow][bcol+4] = rb1;
    __syncthreads();

    for (int k0 = 16; ; k0 += 16) {
        bool more = (k0 < K);
        if (more) {
            ra  = aval ? *(const float4*)(Aptr + k0) : make_float4(0.f,0.f,0.f,0.f);
            rb0 = *(const float4*)(Bptr + (size_t)k0*ldb);
            rb1 = *(const float4*)(Bptr + (size_t)k0*ldb + 4);
        }
        #pragma unroll
        for (int k = 0; k < 16; k++) {
            float4 a = *(const float4*)&As[buf][k][ty<<2];
            float4 b = *(const float4*)&Bs[buf][k][tx<<2];
            acc[0][0] = fmaf(a.x, b.x, acc[0][0]);
            acc[0][1] = fmaf(a.x, b.y, acc[0][1]);
            acc[0][2] = fmaf(a.x, b.z, acc[0][2]);
            acc[0][3] = fmaf(a.x, b.w, acc[0][3]);
            acc[1][0] = fmaf(a.y, b.x, acc[1][0]);
            acc[1][1] = fmaf(a.y, b.y, acc[1][1]);
            acc[1][2] = fmaf(a.y, b.z, acc[1][2]);
            acc[1][3] = fmaf(a.y, b.w, acc[1][3]);
            acc[2][0] = fmaf(a.z, b.x, acc[2][0]);
            acc[2][1] = fmaf(a.z, b.y, acc[2][1]);
            acc[2][2] = fmaf(a.z, b.z, acc[2][2]);
            acc[2][3] = fmaf(a.z, b.w, acc[2][3]);
            acc[3][0] = fmaf(a.w, b.x, acc[3][0]);
            acc[3][1] = fmaf(a.w, b.y, acc[3][1]);
            acc[3][2] = fmaf(a.w, b.z, acc[3][2]);
            acc[3][3] = fmaf(a.w, b.w, acc[3][3]);
        }
        if (!more) break;
        buf ^= 1;
        As[buf][acol  ][arow] = ra.x; As[buf][acol+1][arow] = ra.y;
        As[buf][acol+2][arow] = ra.z; As[buf][acol+3][arow] = ra.w;
        *(float4*)&Bs[buf][brow][bcol]   = rb0;
        *(float4*)&Bs[buf][brow][bcol+4] = rb1;
        __syncthreads();
    }

    if (flags & FLAG_RAW) {
        #pragma unroll
        for (int i = 0; i < 4; i++) {
            int m = m0 + (ty<<2) + i;
            if (m >= M) break;
            *(float4*)(Cz + (size_t)m*ldc + n0 + (tx<<2)) =
                make_float4(acc[i][0], acc[i][1], acc[i][2], acc[i][3]);
        }
        return;
    }
    float4 bv = *(const float4*)(bias + n0 + (tx<<2));
    #pragma unroll
    for (int i = 0; i < 4; i++) {
        int m = m0 + (ty<<2) + i;
        if (m >= M) break;
        float4 v = make_float4(acc[i][0]+bv.x, acc[i][1]+bv.y,
                               acc[i][2]+bv.z, acc[i][3]+bv.w);
        if (flags & FLAG_RELU) {
            v.x = fmaxf(v.x,0.f); v.y = fmaxf(v.y,0.f);
            v.z = fmaxf(v.z,0.f); v.w = fmaxf(v.w,0.f);
        }
        float4* cp = (float4*)(C + (size_t)m*ldc + n0 + (tx<<2));
        if (flags & FLAG_ADD) {
            float4 o = *cp;
            v.x += o.x; v.y += o.y; v.z += o.z; v.w += o.w;
        }
        *cp = v;
    }
}

// ---------------- split-K reduce: C = op(sum_s part[s] + bias) ------------
__global__ void __launch_bounds__(256) reduce_kernel(
        const float* __restrict__ part, const float* __restrict__ bias,
        float* __restrict__ C, int MN, int N, int S, int flags) {
    int idx = (blockIdx.x*256 + threadIdx.x) << 2;
    if (idx >= MN) return;
    float4 v = *(const float4*)(part + idx);
    for (int s = 1; s < S; s++) {
        float4 p = *(const float4*)(part + (size_t)s*MN + idx);
        v.x += p.x; v.y += p.y; v.z += p.z; v.w += p.w;
    }
    float4 bv = *(const float4*)(bias + (idx % N));
    v.x += bv.x; v.y += bv.y; v.z += bv.z; v.w += bv.w;
    if (flags & FLAG_RELU) {
        v.x = fmaxf(v.x,0.f); v.y = fmaxf(v.y,0.f);
        v.z = fmaxf(v.z,0.f); v.w = fmaxf(v.w,0.f);
    }
    float4* cp = (float4*)(C + idx);
    if (flags & FLAG_ADD) {
        float4 o = *cp;
        v.x += o.x; v.y += o.y; v.z += o.z; v.w += o.w;
    }
    *cp = v;
}

// ---------------- layernorm (one block per row) ----------------
__global__ void ln_kernel(const float* __restrict__ x, float* __restrict__ y,
                          const float* __restrict__ g, const float* __restrict__ b) {
    int row = blockIdx.x, t = threadIdx.x;     // 256 threads
    const float* xr = x + (size_t)row*DIMM;
    float v0 = xr[t], v1 = xr[t+256];
    float2 s = blockReduce2_256(v0+v1, v0*v0+v1*v1);
    float mean = s.x * (1.f/512.f);
    float inv  = rsqrtf(s.y*(1.f/512.f) - mean*mean + 1e-5f);
    y[(size_t)row*DIMM + t]       = (v0-mean)*inv*g[t]     + b[t];
    y[(size_t)row*DIMM + t + 256] = (v1-mean)*inv*g[t+256] + b[t+256];
}

// ---------------- fused attention: QK^T + CPB bias + softmax + AV ---------
// One CTA per (head, 32-row i-block). Logits tile lives entirely in smem.
// Dynamic smem: Qs[64][36] + Ks[64][68] (aliased by Vs[32][68]) +
//               S[32][SROW] + sinv[32]  (~80.5 KB)
__global__ void __launch_bounds__(256) attn_kernel(const float* __restrict__ tab) {
    extern __shared__ float smem[];
    float (*Qs)[36]   = (float(*)[36])smem;                        // 2304
    float (*Ks)[68]   = (float(*)[68])(smem + 64*36);              // 4352
    float (*Vs)[68]   = (float(*)[68])(smem + 64*36);              // alias
    float (*S)[SROW]  = (float(*)[SROW])(smem + 64*36 + 64*68);    // 13440
    float* sinv       = smem + 64*36 + 64*68 + 32*SROW;            // 32

    int h  = blockIdx.y;
    int i0 = blockIdx.x << 5;
    int t  = threadIdx.x;
    int tx = t & 15, ty = t >> 4;

    // load Q tile (32 x 64) transposed
    {
        int r = t >> 3, c = (t & 7) << 3;
        const float* qp = g_qkv + (size_t)(i0+r)*QKV3 + h*HDIM + c;
        bool v = (i0 + r) < NTOK;
        float4 z4 = make_float4(0.f,0.f,0.f,0.f);
        float4 x0 = v ? *(const float4*)qp       : z4;
        float4 x1 = v ? *(const float4*)(qp + 4) : z4;
        Qs[c  ][r] = x0.x; Qs[c+1][r] = x0.y; Qs[c+2][r] = x0.z; Qs[c+3][r] = x0.w;
        Qs[c+4][r] = x1.x; Qs[c+5][r] = x1.y; Qs[c+6][r] = x1.z; Qs[c+7][r] = x1.w;
    }

    // phase 1: scores + bias into S
    for (int j0 = 0; j0 < NTOK; j0 += 64) {
        __syncthreads();                       // protect Ks reuse
        {
            int r = t >> 2, c = (t & 3) << 4;
            const float* kp = g_qkv + (size_t)(j0+r)*QKV3 + DIMM + h*HDIM + c;
            bool v = (j0 + r) < NTOK;
            #pragma unroll
            for (int q = 0; q < 4; q++) {
                float4 x = v ? *(const float4*)(kp + (q<<2)) : make_float4(0.f,0.f,0.f,0.f);
                int d = c + (q<<2);
                Ks[d  ][r] = x.x; Ks[d+1][r] = x.y;
                Ks[d+2][r] = x.z; Ks[d+3][r] = x.w;
            }
        }
        __syncthreads();
        float acc[2][4] = {};
        #pragma unroll 8
        for (int d = 0; d < 64; d++) {
            float q0 = Qs[d][ty], q1 = Qs[d][ty+16];
            float4 b = *(const float4*)&Ks[d][tx<<2];
            acc[0][0] = fmaf(q0, b.x, acc[0][0]);
            acc[0][1] = fmaf(q0, b.y, acc[0][1]);
            acc[0][2] = fmaf(q0, b.z, acc[0][2]);
            acc[0][3] = fmaf(q0, b.w, acc[0][3]);
            acc[1][0] = fmaf(q1, b.x, acc[1][0]);
            acc[1][1] = fmaf(q1, b.y, acc[1][1]);
            acc[1][2] = fmaf(q1, b.z, acc[1][2]);
            acc[1][3] = fmaf(q1, b.w, acc[1][3]);
        }
        #pragma unroll
        for (int qi = 0; qi < 2; qi++) {
            int il = ty + (qi<<4);
            int i  = i0 + il;
            #pragma unroll
            for (int qj = 0; qj < 4; qj++) {
                int j = j0 + (tx<<2) + qj;
                if (j < NTOK) {
                    float val = 0.f;
                    if (i < NTOK) {
                        size_t p = (size_t)i*NTOK + j;
                        float pos = g_angpos[p];
                        int   ip  = (int)pos;
                        float f   = pos - (float)ip;
                        const float* r0 = tab + (size_t)ip*8 + h;
                        float bias = r0[0] + f*(r0[8] - r0[0]);
                        val = fmaf(0.125f, acc[qi][qj], bias);
                    }
                    S[il][j] = val;
                }
            }
        }
    }
    __syncthreads();

    // phase 2: row max, exp in place (zeros in padding), 1/sum
    {
        int row = t >> 3, k8 = t & 7;
        float m = -1e30f;
        for (int j = k8; j < NTOK; j += 8) m = fmaxf(m, S[row][j]);
        #pragma unroll
        for (int o = 1; o < 8; o <<= 1)
            m = fmaxf(m, __shfl_xor_sync(0xffffffffu, m, o));
        float s = 0.f;
        for (int j = k8; j < SROW; j += 8) {
            float val = (j < NTOK) ? __expf(S[row][j] - m) : 0.f;
            S[row][j] = val;
            s += val;
        }
        #pragma unroll
        for (int o = 1; o < 8; o <<= 1)
            s += __shfl_xor_sync(0xffffffffu, s, o);
        if (k8 == 0) sinv[row] = 1.f / s;
    }
    __syncthreads();

    // phase 3: AV from smem S (Vs aliases Ks region)
    int d4 = tx << 2;
    int vr = t >> 3, vc = (t & 7) << 3;
    float acc[2][4] = {};
    for (int j0 = 0; j0 < NTOK; j0 += 32) {
        {
            const float* vp = g_qkv + (size_t)(j0+vr)*QKV3 + 2*DIMM + h*HDIM + vc;
            bool vi = (j0 + vr < NTOK);
            float4 z4 = make_float4(0.f,0.f,0.f,0.f);
            float4 v0 = vi ? *(const float4*)vp       : z4;
            float4 v1 = vi ? *(const float4*)(vp + 4) : z4;
            *(float4*)&Vs[vr][vc]   = v0;
            *(float4*)&Vs[vr][vc+4] = v1;
        }
        __syncthreads();
        #pragma unroll
        for (int j = 0; j < 32; j++) {
            float a0 = S[ty][j0+j], a1 = S[ty+16][j0+j];
            float4 vv = *(const float4*)&Vs[j][d4];
            acc[0][0] = fmaf(a0, vv.x, acc[0][0]);
            acc[0][1] = fmaf(a0, vv.y, acc[0][1]);
            acc[0][2] = fmaf(a0, vv.z, acc[0][2]);
            acc[0][3] = fmaf(a0, vv.w, acc[0][3]);
            acc[1][0] = fmaf(a1, vv.x, acc[1][0]);
            acc[1][1] = fmaf(a1, vv.y, acc[1][1]);
            acc[1][2] = fmaf(a1, vv.z, acc[1][2]);
            acc[1][3] = fmaf(a1, vv.w, acc[1][3]);
        }
        __syncthreads();
    }
    #pragma unroll
    for (int q = 0; q < 2; q++) {
        int i = i0 + ty + (q<<4);
        if (i < NTOK) {
            float inv = sinv[ty + (q<<4)];
            *(float4*)(g_ao + (size_t)i*DIMM + h*HDIM + d4) =
                make_float4(acc[q][0]*inv, acc[q][1]*inv,
                            acc[q][2]*inv, acc[q][3]*inv);
        }
    }
}

// ---------------- final: LN(row 0) -> fc2 -> out[2] ----------------
__global__ void final_kernel(const float* __restrict__ g, const float* __restrict__ b,
                             const float* __restrict__ w, const float* __restrict__ bias,
                             float* __restrict__ out) {
    int t = threadIdx.x;                  // 256 threads
    float v0 = g_h[t], v1 = g_h[t+256];
    float2 s = blockReduce2_256(v0+v1, v0*v0+v1*v1);
    float mean = s.x * (1.f/512.f);
    float inv  = rsqrtf(s.y*(1.f/512.f) - mean*mean + 1e-5f);
    float l0 = (v0-mean)*inv*g[t]     + b[t];
    float l1 = (v1-mean)*inv*g[t+256] + b[t+256];
    float p0 = l0*w[t*2]   + l1*w[(t+256)*2];
    float p1 = l0*w[t*2+1] + l1*w[(t+256)*2+1];
    float2 sp = blockReduce2_256(p0, p1);
    if (t == 0) { out[0] = sp.x + bias[0]; out[1] = sp.y + bias[1]; }
}

// ---------------- launch ----------------
extern "C" void kernel_launch(void* const* d_in, const int* in_sizes, int n_in,
                              void* d_out, int out_size) {
    const float* h_in   = (const float*)d_in[0];
    const float* coords = (const float*)d_in[1];
    const float* fc1_w  = (const float*)d_in[2];
    const float* fc1_b  = (const float*)d_in[3];
    const float* cls    = (const float*)d_in[4];
    const float* norm_g = (const float*)d_in[25];
    const float* norm_b = (const float*)d_in[26];
    const float* fc2_w  = (const float*)d_in[27];
    const float* fc2_b  = (const float*)d_in[28];

    float *p_h, *p_ln, *p_qkv, *p_ao, *p_part, *p_tab[2];
    cudaGetSymbolAddress((void**)&p_h,      g_h);
    cudaGetSymbolAddress((void**)&p_ln,     g_ln);
    cudaGetSymbolAddress((void**)&p_qkv,    g_qkv);
    cudaGetSymbolAddress((void**)&p_ao,     g_ao);
    cudaGetSymbolAddress((void**)&p_part,   g_part);
    cudaGetSymbolAddress((void**)&p_tab[0], g_table0);
    cudaGetSymbolAddress((void**)&p_tab[1], g_table1);

    const int ATTN_SMEM = (64*36 + 64*68 + 32*SROW + 32) * 4;  // ~80.5 KB
    cudaFuncSetAttribute(attn_kernel,
                         cudaFuncAttributeMaxDynamicSharedMemorySize, ATTN_SMEM);

    setup_kernel<<<4, 256>>>(cls, coords);
    angpos_kernel<<<(NPAIR + 255)/256, 256>>>();
    cpb_table_kernel<<<dim3((TABN + 3 + 31)/32, 2), 256>>>(
        (const float*)d_in[7],  (const float*)d_in[8],
        (const float*)d_in[9],  (const float*)d_in[10], p_tab[0],
        (const float*)d_in[17], (const float*)d_in[18],
        (const float*)d_in[19], (const float*)d_in[20], p_tab[1]);

    // fc1: split-K x8 (K=1024 -> 8x128), reduce+bias+relu
    gemm_kernel<<<dim3(DIMM/64, (NPT+31)/32, 8), 128>>>(
        h_in, 1024, fc1_w, DIMM, (const float*)0,
        p_part, DIMM, NPT, DIMM, 128, FLAG_RAW);
    reduce_kernel<<<(NPT*DIMM/4 + 255)/256, 256>>>(
        p_part, fc1_b, p_h + DIMM, NPT*DIMM, DIMM, 8, FLAG_RELU);

    for (int L = 0; L < 2; L++) {
        const float* lp[10];
        for (int q = 0; q < 10; q++) lp[q] = (const float*)d_in[5 + L*10 + q];
        const float* ln_g   = lp[0]; const float* ln_b   = lp[1];
        const float* qkv_w  = lp[6]; const float* qkv_b  = lp[7];
        const float* proj_w = lp[8]; const float* proj_b = lp[9];

        ln_kernel<<<NTOK, 256>>>(p_h, p_ln, ln_g, ln_b);
        // qkv: split-K x4 (K=512 -> 4x128), reduce+bias
        gemm_kernel<<<dim3(QKV3/64, (NTOK+31)/32, 4), 128>>>(
            p_ln, DIMM, qkv_w, QKV3, (const float*)0,
            p_part, QKV3, NTOK, QKV3, 128, FLAG_RAW);
        reduce_kernel<<<(NTOK*QKV3/4 + 255)/256, 256>>>(
            p_part, qkv_b, p_qkv, NTOK*QKV3, QKV3, 4, 0);
        // fused attention (scores + bias + softmax + AV)
        attn_kernel<<<dim3(13, NHEAD), 256, ATTN_SMEM>>>(p_tab[L]);
        // proj: split-K x4 (K=512 -> 4x128), reduce+bias+residual
        gemm_kernel<<<dim3(DIMM/64, (NTOK+31)/32, 4), 128>>>(
            p_ao, DIMM, proj_w, DIMM, (const float*)0,
            p_part, DIMM, NTOK, DIMM, 128, FLAG_RAW);
        reduce_kernel<<<(NTOK*DIMM/4 + 255)/256, 256>>>(
            p_part, proj_b, p_h, NTOK*DIMM, DIMM, 4, FLAG_ADD);
    }

    final_kernel<<<1, 256>>>(norm_g, norm_b, fc2_w, fc2_b, (float*)d_out);
}

// round 13
// speedup vs baseline: 1.0578x; 1.0578x over previous
#include <cuda_runtime.h>
#include <math.h>

#define NTOK 401
#define NPT  400
#define DIMM 512
#define NHEAD 8
#define HDIM 64
#define QKV3 1536
#define CPBH 512
#define NPAIR (NTOK*NTOK)
#define TABN 4096
#define PI_F 3.14159265358979323846f
#define FLAG_RELU 1
#define FLAG_ADD  2
#define FLAG_RAW  4

// ---------------- scratch (alloc-free, __device__ globals) ----------------
__device__ float  g_h[NTOK*DIMM];          // residual stream
__device__ float  g_ln[NTOK*DIMM];         // layernorm output
__device__ float  g_qkv[NTOK*QKV3];        // fused qkv
__device__ float  g_attn[NHEAD*NTOK*NTOK]; // attention logits (5.1 MB)
__device__ float  g_ao[NTOK*DIMM];         // attention output (pre-proj)
__device__ float  g_part[8*NTOK*DIMM];     // split-K partials (6.6 MB)
__device__ float  g_angpos[NPAIR];         // table position per pair (both layers)
__device__ float  g_coords[NTOK*2];
__device__ float  g_table0[(TABN+4)*8];    // layer-1 bias table
__device__ float  g_table1[(TABN+4)*8];    // layer-2 bias table

// ---------------- small helpers ----------------
__device__ __forceinline__ float2 blockReduce2_256(float a, float b) {
    __shared__ float sa[8], sb[8];
    __syncthreads();
    #pragma unroll
    for (int o = 16; o > 0; o >>= 1) {
        a += __shfl_xor_sync(0xffffffffu, a, o);
        b += __shfl_xor_sync(0xffffffffu, b, o);
    }
    int w = threadIdx.x >> 5;
    if ((threadIdx.x & 31) == 0) { sa[w] = a; sb[w] = b; }
    __syncthreads();
    a = sa[0]+sa[1]+sa[2]+sa[3]+sa[4]+sa[5]+sa[6]+sa[7];
    b = sb[0]+sb[1]+sb[2]+sb[3]+sb[4]+sb[5]+sb[6]+sb[7];
    return make_float2(a, b);
}

// ---------------- setup: CLS row + coords (CLS coord = 0) ----------------
__global__ void setup_kernel(const float* __restrict__ cls,
                             const float* __restrict__ coords) {
    int t = blockIdx.x*blockDim.x + threadIdx.x;
    if (t < DIMM)  g_h[t] = cls[t];
    if (t < 2)     g_coords[t] = 0.f;
    if (t < NPT*2) g_coords[2+t] = coords[t];
}

// ---------------- per-pair angle table position ----------------
__global__ void angpos_kernel() {
    int p = blockIdx.x*blockDim.x + threadIdx.x;
    if (p >= NPAIR) return;
    int i = p / NTOK, j = p - i*NTOK;
    float pos;
    if (i == j) {
        pos = (float)(TABN + 1);           // diag: dir = (0,0) special row
    } else {
        float dx = g_coords[2*i]   - g_coords[2*j];
        float dy = g_coords[2*i+1] - g_coords[2*j+1];
        float th = atan2f(dy, dx);
        pos = (th + PI_F) * ((float)TABN / (2.0f*PI_F));
        pos = fminf(fmaxf(pos, 0.f), (float)TABN);
    }
    g_angpos[p] = pos;
}

// ---------------- build CPB bias tables (both layers, grid.y selects) ----
__global__ void __launch_bounds__(256) cpb_table_kernel(
        const float* __restrict__ w1a, const float* __restrict__ b1a,
        const float* __restrict__ w2a, const float* __restrict__ b2a,
        float* __restrict__ outa,
        const float* __restrict__ w1b, const float* __restrict__ b1b,
        const float* __restrict__ w2b, const float* __restrict__ b2b,
        float* __restrict__ outb) {
    const float* w1 = blockIdx.y ? w1b : w1a;
    const float* b1 = blockIdx.y ? b1b : b1a;
    const float* w2 = blockIdx.y ? w2b : w2a;
    const float* b2 = blockIdx.y ? b2b : b2a;
    float*      out = blockIdx.y ? outb : outa;

    __shared__ float swx[CPBH], swy[CPBH], sbb[CPBH];
    __shared__ __align__(16) float sw2[CPBH*8];
    __shared__ float sred[8][32][9];
    int t = threadIdx.x;
    for (int c = t; c < CPBH; c += 256) {
        swx[c] = w1[c]; swy[c] = w1[CPBH + c]; sbb[c] = b1[c];
    }
    for (int c = t; c < CPBH*2; c += 256)
        *(float4*)(sw2 + c*4) = *(const float4*)(w2 + c*4);
    __syncthreads();

    int e = t & 31;
    int w = t >> 5;
    int idx = blockIdx.x*32 + e;
    float ux = 0.f, uy = 0.f;
    if (idx <= TABN) {
        float th = -PI_F + (2.0f*PI_F) * ((float)idx / (float)TABN);
        sincosf(th, &uy, &ux);
    }
    float acc[8] = {0.f,0.f,0.f,0.f,0.f,0.f,0.f,0.f};
    int c0 = w << 6;
    #pragma unroll 8
    for (int cc = 0; cc < 64; cc++) {
        int c = c0 + cc;
        float hv = fmaf(ux, swx[c], fmaf(uy, swy[c], sbb[c]));
        hv = fmaxf(hv, 0.f);
        float4 wa = *(const float4*)(sw2 + (c<<3));
        float4 wb = *(const float4*)(sw2 + (c<<3) + 4);
        acc[0] = fmaf(hv, wa.x, acc[0]);
        acc[1] = fmaf(hv, wa.y, acc[1]);
        acc[2] = fmaf(hv, wa.z, acc[2]);
        acc[3] = fmaf(hv, wa.w, acc[3]);
        acc[4] = fmaf(hv, wb.x, acc[4]);
        acc[5] = fmaf(hv, wb.y, acc[5]);
        acc[6] = fmaf(hv, wb.z, acc[6]);
        acc[7] = fmaf(hv, wb.w, acc[7]);
    }
    #pragma unroll
    for (int k = 0; k < 8; k++) sred[w][e][k] = acc[k];
    __syncthreads();

    int re = t >> 3, rk = t & 7;
    float s = 0.f;
    #pragma unroll
    for (int ww = 0; ww < 8; ww++) s += sred[ww][re][rk];
    int ridx = blockIdx.x*32 + re;
    if (ridx <= TABN + 2) {
        float v = (ridx == TABN + 2) ? 0.f : s + b2[rk];
        out[(size_t)ridx*8 + rk] = v;
    }
}

// ---------------- 32x64-tile fp32 GEMM, 128 threads, 4x4/thread -----------
// CTA-level split-K via blockIdx.z; with FLAG_RAW partials to C + z*M*ldc.
__global__ void __launch_bounds__(128) gemm_kernel(
        const float* __restrict__ A, int lda,
        const float* __restrict__ B, int ldb,
        const float* __restrict__ bias,
        float* __restrict__ C, int ldc,
        int M, int N, int K, int flags) {
    __shared__ __align__(16) float As[2][16][36];
    __shared__ __align__(16) float Bs[2][16][68];
    int t  = threadIdx.x;
    int m0 = blockIdx.y << 5, n0 = blockIdx.x << 6;
    int zi = blockIdx.z;
    const float* Az = A + (size_t)zi*K;
    const float* Bz = B + (size_t)zi*K*ldb;
    float* Cz = C + (size_t)zi*M*ldc;
    int arow = t >> 2, acol = (t & 3) << 2;
    int brow = t >> 3, bcol = (t & 7) << 3;
    int tx = t & 15, ty = t >> 4;
    float acc[4][4] = {};

    bool aval = (m0 + arow) < M;
    const float* Aptr = Az + (size_t)(m0 + arow)*lda + acol;
    const float* Bptr = Bz + (size_t)brow*ldb + n0 + bcol;

    float4 ra  = aval ? *(const float4*)Aptr : make_float4(0.f,0.f,0.f,0.f);
    float4 rb0 = *(const float4*)Bptr;
    float4 rb1 = *(const float4*)(Bptr + 4);
    int buf = 0;
    As[0][acol  ][arow] = ra.x; As[0][acol+1][arow] = ra.y;
    As[0][acol+2][arow] = ra.z; As[0][acol+3][arow] = ra.w;
    *(float4*)&Bs[0][brow][bcol]   = rb0;
    *(float4*)&Bs[0][brow][bcol+4] = rb1;
    __syncthreads();

    for (int k0 = 16; ; k0 += 16) {
        bool more = (k0 < K);
        if (more) {
            ra  = aval ? *(const float4*)(Aptr + k0) : make_float4(0.f,0.f,0.f,0.f);
            rb0 = *(const float4*)(Bptr + (size_t)k0*ldb);
            rb1 = *(const float4*)(Bptr + (size_t)k0*ldb + 4);
        }
        #pragma unroll
        for (int k = 0; k < 16; k++) {
            float4 a = *(const float4*)&As[buf][k][ty<<2];
            float4 b = *(const float4*)&Bs[buf][k][tx<<2];
            acc[0][0] = fmaf(a.x, b.x, acc[0][0]);
            acc[0][1] = fmaf(a.x, b.y, acc[0][1]);
            acc[0][2] = fmaf(a.x, b.z, acc[0][2]);
            acc[0][3] = fmaf(a.x, b.w, acc[0][3]);
            acc[1][0] = fmaf(a.y, b.x, acc[1][0]);
            acc[1][1] = fmaf(a.y, b.y, acc[1][1]);
            acc[1][2] = fmaf(a.y, b.z, acc[1][2]);
            acc[1][3] = fmaf(a.y, b.w, acc[1][3]);
            acc[2][0] = fmaf(a.z, b.x, acc[2][0]);
            acc[2][1] = fmaf(a.z, b.y, acc[2][1]);
            acc[2][2] = fmaf(a.z, b.z, acc[2][2]);
            acc[2][3] = fmaf(a.z, b.w, acc[2][3]);
            acc[3][0] = fmaf(a.w, b.x, acc[3][0]);
            acc[3][1] = fmaf(a.w, b.y, acc[3][1]);
            acc[3][2] = fmaf(a.w, b.z, acc[3][2]);
            acc[3][3] = fmaf(a.w, b.w, acc[3][3]);
        }
        if (!more) break;
        buf ^= 1;
        As[buf][acol  ][arow] = ra.x; As[buf][acol+1][arow] = ra.y;
        As[buf][acol+2][arow] = ra.z; As[buf][acol+3][arow] = ra.w;
        *(float4*)&Bs[buf][brow][bcol]   = rb0;
        *(float4*)&Bs[buf][brow][bcol+4] = rb1;
        __syncthreads();
    }

    if (flags & FLAG_RAW) {
        #pragma unroll
        for (int i = 0; i < 4; i++) {
            int m = m0 + (ty<<2) + i;
            if (m >= M) break;
            *(float4*)(Cz + (size_t)m*ldc + n0 + (tx<<2)) =
                make_float4(acc[i][0], acc[i][1], acc[i][2], acc[i][3]);
        }
        return;
    }
    float4 bv = *(const float4*)(bias + n0 + (tx<<2));
    #pragma unroll
    for (int i = 0; i < 4; i++) {
        int m = m0 + (ty<<2) + i;
        if (m >= M) break;
        float4 v = make_float4(acc[i][0]+bv.x, acc[i][1]+bv.y,
                               acc[i][2]+bv.z, acc[i][3]+bv.w);
        if (flags & FLAG_RELU) {
            v.x = fmaxf(v.x,0.f); v.y = fmaxf(v.y,0.f);
            v.z = fmaxf(v.z,0.f); v.w = fmaxf(v.w,0.f);
        }
        float4* cp = (float4*)(C + (size_t)m*ldc + n0 + (tx<<2));
        if (flags & FLAG_ADD) {
            float4 o = *cp;
            v.x += o.x; v.y += o.y; v.z += o.z; v.w += o.w;
        }
        *cp = v;
    }
}

// ---------------- split-K reduce: C = op(sum_s part[s] + bias) ------------
__global__ void __launch_bounds__(256) reduce_kernel(
        const float* __restrict__ part, const float* __restrict__ bias,
        float* __restrict__ C, int MN, int N, int S, int flags) {
    int idx = (blockIdx.x*256 + threadIdx.x) << 2;
    if (idx >= MN) return;
    float4 v = *(const float4*)(part + idx);
    for (int s = 1; s < S; s++) {
        float4 p = *(const float4*)(part + (size_t)s*MN + idx);
        v.x += p.x; v.y += p.y; v.z += p.z; v.w += p.w;
    }
    float4 bv = *(const float4*)(bias + (idx % N));
    v.x += bv.x; v.y += bv.y; v.z += bv.z; v.w += bv.w;
    if (flags & FLAG_RELU) {
        v.x = fmaxf(v.x,0.f); v.y = fmaxf(v.y,0.f);
        v.z = fmaxf(v.z,0.f); v.w = fmaxf(v.w,0.f);
    }
    float4* cp = (float4*)(C + idx);
    if (flags & FLAG_ADD) {
        float4 o = *cp;
        v.x += o.x; v.y += o.y; v.z += o.z; v.w += o.w;
    }
    *cp = v;
}

// ---------------- layernorm (one block per row) ----------------
__global__ void ln_kernel(const float* __restrict__ x, float* __restrict__ y,
                          const float* __restrict__ g, const float* __restrict__ b) {
    int row = blockIdx.x, t = threadIdx.x;     // 256 threads
    const float* xr = x + (size_t)row*DIMM;
    float v0 = xr[t], v1 = xr[t+256];
    float2 s = blockReduce2_256(v0+v1, v0*v0+v1*v1);
    float mean = s.x * (1.f/512.f);
    float inv  = rsqrtf(s.y*(1.f/512.f) - mean*mean + 1e-5f);
    y[(size_t)row*DIMM + t]       = (v0-mean)*inv*g[t]     + b[t];
    y[(size_t)row*DIMM + t + 256] = (v1-mean)*inv*g[t+256] + b[t+256];
}

// ---------------- QK^T scores + fused CPB bias ----------------
__global__ void __launch_bounds__(128) scores_kernel(const float* __restrict__ tab) {
    __shared__ __align__(16) float Qs[64][36];   // [d][i]
    __shared__ __align__(16) float Ks[64][68];   // [d][j]
    int h  = blockIdx.z;
    int i0 = blockIdx.y << 5, j0 = blockIdx.x << 6;
    int t  = threadIdx.x;

    {
        int r = t >> 2, c = (t & 3) << 4;
        const float* qp = g_qkv + (size_t)(i0+r)*QKV3 + h*HDIM + c;
        bool v = (i0 + r) < NTOK;
        #pragma unroll
        for (int q = 0; q < 4; q++) {
            float4 x = v ? *(const float4*)(qp + (q<<2)) : make_float4(0.f,0.f,0.f,0.f);
            int d = c + (q<<2);
            Qs[d  ][r] = x.x; Qs[d+1][r] = x.y;
            Qs[d+2][r] = x.z; Qs[d+3][r] = x.w;
        }
    }
    {
        int r = t >> 1, c = (t & 1) << 5;
        const float* kp = g_qkv + (size_t)(j0+r)*QKV3 + DIMM + h*HDIM + c;
        bool v = (j0 + r) < NTOK;
        #pragma unroll
        for (int q = 0; q < 8; q++) {
            float4 x = v ? *(const float4*)(kp + (q<<2)) : make_float4(0.f,0.f,0.f,0.f);
            int d = c + (q<<2);
            Ks[d  ][r] = x.x; Ks[d+1][r] = x.y;
            Ks[d+2][r] = x.z; Ks[d+3][r] = x.w;
        }
    }
    __syncthreads();

    int tx = t & 15, ty = t >> 4;
    float acc[4][4] = {};
    #pragma unroll 8
    for (int d = 0; d < 64; d++) {
        float4 a = *(const float4*)&Qs[d][ty<<2];
        float4 b = *(const float4*)&Ks[d][tx<<2];
        acc[0][0] = fmaf(a.x, b.x, acc[0][0]);
        acc[0][1] = fmaf(a.x, b.y, acc[0][1]);
        acc[0][2] = fmaf(a.x, b.z, acc[0][2]);
        acc[0][3] = fmaf(a.x, b.w, acc[0][3]);
        acc[1][0] = fmaf(a.y, b.x, acc[1][0]);
        acc[1][1] = fmaf(a.y, b.y, acc[1][1]);
        acc[1][2] = fmaf(a.y, b.z, acc[1][2]);
        acc[1][3] = fmaf(a.y, b.w, acc[1][3]);
        acc[2][0] = fmaf(a.z, b.x, acc[2][0]);
        acc[2][1] = fmaf(a.z, b.y, acc[2][1]);
        acc[2][2] = fmaf(a.z, b.z, acc[2][2]);
        acc[2][3] = fmaf(a.z, b.w, acc[2][3]);
        acc[3][0] = fmaf(a.w, b.x, acc[3][0]);
        acc[3][1] = fmaf(a.w, b.y, acc[3][1]);
        acc[3][2] = fmaf(a.w, b.z, acc[3][2]);
        acc[3][3] = fmaf(a.w, b.w, acc[3][3]);
    }

    #pragma unroll
    for (int qi = 0; qi < 4; qi++) {
        int i = i0 + (ty<<2) + qi;
        if (i >= NTOK) break;
        #pragma unroll
        for (int qj = 0; qj < 4; qj++) {
            int j = j0 + (tx<<2) + qj;
            if (j < NTOK) {
                size_t p = (size_t)i*NTOK + j;
                float pos = g_angpos[p];
                int   ip  = (int)pos;
                float f   = pos - (float)ip;
                const float* r0 = tab + (size_t)ip*8 + h;
                float bias = r0[0] + f*(r0[8] - r0[0]);
                g_attn[(size_t)h*NTOK*NTOK + p] = fmaf(0.125f, acc[qi][qj], bias);
            }
        }
    }
}

// ---------------- fused softmax + attn@V (per-head, 32 i-rows) ------------
__global__ void __launch_bounds__(256) softav_kernel() {
    __shared__ float sa[32][33];
    __shared__ __align__(16) float sv[32][68];
    __shared__ float smx[32], sinv[32];
    int h  = blockIdx.y;
    int i0 = blockIdx.x << 5;
    int t  = threadIdx.x;

    {
        int row = t >> 3, k8 = t & 7;
        int gi  = i0 + row;
        int cgi = gi < NTOK ? gi : NTOK - 1;
        const float* arow = g_attn + ((size_t)h*NTOK + cgi)*NTOK;
        float m = -1e30f;
        for (int j = k8; j < NTOK; j += 8) m = fmaxf(m, arow[j]);
        #pragma unroll
        for (int o = 1; o < 8; o <<= 1)
            m = fmaxf(m, __shfl_xor_sync(0xffffffffu, m, o));
        float s = 0.f;
        for (int j = k8; j < NTOK; j += 8) s += __expf(arow[j] - m);
        #pragma unroll
        for (int o = 1; o < 8; o <<= 1)
            s += __shfl_xor_sync(0xffffffffu, s, o);
        if (k8 == 0) { smx[row] = m; sinv[row] = 1.f / s; }
    }
    __syncthreads();

    int tx = t & 15, ty = t >> 4;
    int d4 = tx << 2;
    int ar = t >> 3, ac = (t & 7) << 2;
    int vr = t >> 3, vc = (t & 7) << 3;
    float mrow = smx[ar];
    float acc[2][4] = {};
    for (int j0 = 0; j0 < NTOK; j0 += 32) {
        #pragma unroll
        for (int q = 0; q < 4; q++) {
            int i = i0 + ar, j = j0 + ac + q;
            float e = 0.f;
            if (i < NTOK && j < NTOK)
                e = __expf(g_attn[((size_t)h*NTOK + i)*NTOK + j] - mrow);
            sa[ar][ac+q] = e;
        }
        {
            const float* vp = g_qkv + (size_t)(j0+vr)*QKV3 + 2*DIMM + h*HDIM + vc;
            bool vi = (j0 + vr < NTOK);
            float4 z = make_float4(0.f,0.f,0.f,0.f);
            float4 v0 = vi ? *(const float4*)vp       : z;
            float4 v1 = vi ? *(const float4*)(vp + 4) : z;
            *(float4*)&sv[vr][vc]   = v0;
            *(float4*)&sv[vr][vc+4] = v1;
        }
        __syncthreads();
        #pragma unroll
        for (int j = 0; j < 32; j++) {
            float4 vv = *(const float4*)&sv[j][d4];
            float a0 = sa[ty][j], a1 = sa[ty+16][j];
            acc[0][0] = fmaf(a0, vv.x, acc[0][0]);
            acc[0][1] = fmaf(a0, vv.y, acc[0][1]);
            acc[0][2] = fmaf(a0, vv.z, acc[0][2]);
            acc[0][3] = fmaf(a0, vv.w, acc[0][3]);
            acc[1][0] = fmaf(a1, vv.x, acc[1][0]);
            acc[1][1] = fmaf(a1, vv.y, acc[1][1]);
            acc[1][2] = fmaf(a1, vv.z, acc[1][2]);
            acc[1][3] = fmaf(a1, vv.w, acc[1][3]);
        }
        __syncthreads();
    }
    #pragma unroll
    for (int q = 0; q < 2; q++) {
        int i = i0 + ty + (q<<4);
        if (i < NTOK) {
            float inv = sinv[ty + (q<<4)];
            *(float4*)(g_ao + (size_t)i*DIMM + h*HDIM + d4) =
                make_float4(acc[q][0]*inv, acc[q][1]*inv,
                            acc[q][2]*inv, acc[q][3]*inv);
        }
    }
}

// ---------------- final: LN(row 0) -> fc2 -> out[2] ----------------
__global__ void final_kernel(const float* __restrict__ g, const float* __restrict__ b,
                             const float* __restrict__ w, const float* __restrict__ bias,
                             float* __restrict__ out) {
    int t = threadIdx.x;                  // 256 threads
    float v0 = g_h[t], v1 = g_h[t+256];
    float2 s = blockReduce2_256(v0+v1, v0*v0+v1*v1);
    float mean = s.x * (1.f/512.f);
    float inv  = rsqrtf(s.y*(1.f/512.f) - mean*mean + 1e-5f);
    float l0 = (v0-mean)*inv*g[t]     + b[t];
    float l1 = (v1-mean)*inv*g[t+256] + b[t+256];
    float p0 = l0*w[t*2]   + l1*w[(t+256)*2];
    float p1 = l0*w[t*2+1] + l1*w[(t+256)*2+1];
    float2 sp = blockReduce2_256(p0, p1);
    if (t == 0) { out[0] = sp.x + bias[0]; out[1] = sp.y + bias[1]; }
}

// ---------------- launch ----------------
extern "C" void kernel_launch(void* const* d_in, const int* in_sizes, int n_in,
                              void* d_out, int out_size) {
    const float* h_in   = (const float*)d_in[0];
    const float* coords = (const float*)d_in[1];
    const float* fc1_w  = (const float*)d_in[2];
    const float* fc1_b  = (const float*)d_in[3];
    const float* cls    = (const float*)d_in[4];
    const float* norm_g = (const float*)d_in[25];
    const float* norm_b = (const float*)d_in[26];
    const float* fc2_w  = (const float*)d_in[27];
    const float* fc2_b  = (const float*)d_in[28];

    float *p_h, *p_ln, *p_qkv, *p_ao, *p_part, *p_tab[2];
    cudaGetSymbolAddress((void**)&p_h,      g_h);
    cudaGetSymbolAddress((void**)&p_ln,     g_ln);
    cudaGetSymbolAddress((void**)&p_qkv,    g_qkv);
    cudaGetSymbolAddress((void**)&p_ao,     g_ao);
    cudaGetSymbolAddress((void**)&p_part,   g_part);
    cudaGetSymbolAddress((void**)&p_tab[0], g_table0);
    cudaGetSymbolAddress((void**)&p_tab[1], g_table1);

    setup_kernel<<<4, 256>>>(cls, coords);
    angpos_kernel<<<(NPAIR + 255)/256, 256>>>();
    cpb_table_kernel<<<dim3((TABN + 3 + 31)/32, 2), 256>>>(
        (const float*)d_in[7],  (const float*)d_in[8],
        (const float*)d_in[9],  (const float*)d_in[10], p_tab[0],
        (const float*)d_in[17], (const float*)d_in[18],
        (const float*)d_in[19], (const float*)d_in[20], p_tab[1]);

    // fc1: split-K x8 (K=1024 -> 8x128), reduce+bias+relu
    gemm_kernel<<<dim3(DIMM/64, (NPT+31)/32, 8), 128>>>(
        h_in, 1024, fc1_w, DIMM, (const float*)0,
        p_part, DIMM, NPT, DIMM, 128, FLAG_RAW);
    reduce_kernel<<<(NPT*DIMM/4 + 255)/256, 256>>>(
        p_part, fc1_b, p_h + DIMM, NPT*DIMM, DIMM, 8, FLAG_RELU);

    for (int L = 0; L < 2; L++) {
        const float* lp[10];
        for (int q = 0; q < 10; q++) lp[q] = (const float*)d_in[5 + L*10 + q];
        const float* ln_g   = lp[0]; const float* ln_b   = lp[1];
        const float* qkv_w  = lp[6]; const float* qkv_b  = lp[7];
        const float* proj_w = lp[8]; const float* proj_b = lp[9];

        ln_kernel<<<NTOK, 256>>>(p_h, p_ln, ln_g, ln_b);
        // qkv: split-K x2 (K=512 -> 2x256), reduce+bias
        gemm_kernel<<<dim3(QKV3/64, (NTOK+31)/32, 2), 128>>>(
            p_ln, DIMM, qkv_w, QKV3, (const float*)0,
            p_part, QKV3, NTOK, QKV3, 256, FLAG_RAW);
        reduce_kernel<<<(NTOK*QKV3/4 + 255)/256, 256>>>(
            p_part, qkv_b, p_qkv, NTOK*QKV3, QKV3, 2, 0);
        scores_kernel<<<dim3(7, 13, NHEAD), 128>>>(p_tab[L]);
        softav_kernel<<<dim3(13, NHEAD), 256>>>();
        // proj: split-K x4 (K=512 -> 4x128), reduce+bias+residual
        gemm_kernel<<<dim3(DIMM/64, (NTOK+31)/32, 4), 128>>>(
            p_ao, DIMM, proj_w, DIMM, (const float*)0,
            p_part, DIMM, NTOK, DIMM, 128, FLAG_RAW);
        reduce_kernel<<<(NTOK*DIMM/4 + 255)/256, 256>>>(
            p_part, proj_b, p_h, NTOK*DIMM, DIMM, 4, FLAG_ADD);
    }

    final_kernel<<<1, 256>>>(norm_g, norm_b, fc2_w, fc2_b, (float*)d_out);
}

// round 14
// speedup vs baseline: 1.0871x; 1.0276x over previous
#include <cuda_runtime.h>
#include <math.h>

#define NTOK 401
#define NPT  400
#define DIMM 512
#define NHEAD 8
#define HDIM 64
#define QKV3 1536
#define CPBH 512
#define NPAIR (NTOK*NTOK)
#define TABN 4096
#define PI_F 3.14159265358979323846f
#define FLAG_RELU 1
#define FLAG_ADD  2
#define FLAG_RAW  4

// ---------------- scratch (alloc-free, __device__ globals) ----------------
__device__ float  g_h[NTOK*DIMM];          // residual stream
__device__ float  g_ln[NTOK*DIMM];         // layernorm output
__device__ float  g_qkv[NTOK*QKV3];        // fused qkv
__device__ float  g_attn[NHEAD*NTOK*NTOK]; // attention logits (5.1 MB)
__device__ float  g_ao[NTOK*DIMM];         // attention output (pre-proj)
__device__ float  g_part[8*NTOK*DIMM];     // split-K partials (6.6 MB)
__device__ float  g_angpos[NPAIR];         // table position per pair (both layers)
__device__ float  g_table0[(TABN+4)*8];    // layer-1 bias table
__device__ float  g_table1[(TABN+4)*8];    // layer-2 bias table

// ---------------- small helpers ----------------
__device__ __forceinline__ float2 blockReduce2_256(float a, float b) {
    __shared__ float sa[8], sb[8];
    __syncthreads();
    #pragma unroll
    for (int o = 16; o > 0; o >>= 1) {
        a += __shfl_xor_sync(0xffffffffu, a, o);
        b += __shfl_xor_sync(0xffffffffu, b, o);
    }
    int w = threadIdx.x >> 5;
    if ((threadIdx.x & 31) == 0) { sa[w] = a; sb[w] = b; }
    __syncthreads();
    a = sa[0]+sa[1]+sa[2]+sa[3]+sa[4]+sa[5]+sa[6]+sa[7];
    b = sb[0]+sb[1]+sb[2]+sb[3]+sb[4]+sb[5]+sb[6]+sb[7];
    return make_float2(a, b);
}

// ---------------- per-pair angle table position (coords inline) -----------
// token 0 = CLS at origin; token i>=1 uses coords[i-1].
__global__ void angpos_kernel(const float* __restrict__ coords) {
    int p = blockIdx.x*blockDim.x + threadIdx.x;
    if (p >= NPAIR) return;
    int i = p / NTOK, j = p - i*NTOK;
    float pos;
    if (i == j) {
        pos = (float)(TABN + 1);           // diag: dir = (0,0) special row
    } else {
        float xi = (i == 0) ? 0.f : coords[2*(i-1)];
        float yi = (i == 0) ? 0.f : coords[2*(i-1)+1];
        float xj = (j == 0) ? 0.f : coords[2*(j-1)];
        float yj = (j == 0) ? 0.f : coords[2*(j-1)+1];
        float th = atan2f(yi - yj, xi - xj);
        pos = (th + PI_F) * ((float)TABN / (2.0f*PI_F));
        pos = fminf(fmaxf(pos, 0.f), (float)TABN);
    }
    g_angpos[p] = pos;
}

// ---------------- build CPB bias tables (both layers, grid.y selects) ----
__global__ void __launch_bounds__(256) cpb_table_kernel(
        const float* __restrict__ w1a, const float* __restrict__ b1a,
        const float* __restrict__ w2a, const float* __restrict__ b2a,
        float* __restrict__ outa,
        const float* __restrict__ w1b, const float* __restrict__ b1b,
        const float* __restrict__ w2b, const float* __restrict__ b2b,
        float* __restrict__ outb) {
    const float* w1 = blockIdx.y ? w1b : w1a;
    const float* b1 = blockIdx.y ? b1b : b1a;
    const float* w2 = blockIdx.y ? w2b : w2a;
    const float* b2 = blockIdx.y ? b2b : b2a;
    float*      out = blockIdx.y ? outb : outa;

    __shared__ float swx[CPBH], swy[CPBH], sbb[CPBH];
    __shared__ __align__(16) float sw2[CPBH*8];
    __shared__ float sred[8][32][9];
    int t = threadIdx.x;
    for (int c = t; c < CPBH; c += 256) {
        swx[c] = w1[c]; swy[c] = w1[CPBH + c]; sbb[c] = b1[c];
    }
    for (int c = t; c < CPBH*2; c += 256)
        *(float4*)(sw2 + c*4) = *(const float4*)(w2 + c*4);
    __syncthreads();

    int e = t & 31;
    int w = t >> 5;
    int idx = blockIdx.x*32 + e;
    float ux = 0.f, uy = 0.f;
    if (idx <= TABN) {
        float th = -PI_F + (2.0f*PI_F) * ((float)idx / (float)TABN);
        sincosf(th, &uy, &ux);
    }
    float acc[8] = {0.f,0.f,0.f,0.f,0.f,0.f,0.f,0.f};
    int c0 = w << 6;
    #pragma unroll 8
    for (int cc = 0; cc < 64; cc++) {
        int c = c0 + cc;
        float hv = fmaf(ux, swx[c], fmaf(uy, swy[c], sbb[c]));
        hv = fmaxf(hv, 0.f);
        float4 wa = *(const float4*)(sw2 + (c<<3));
        float4 wb = *(const float4*)(sw2 + (c<<3) + 4);
        acc[0] = fmaf(hv, wa.x, acc[0]);
        acc[1] = fmaf(hv, wa.y, acc[1]);
        acc[2] = fmaf(hv, wa.z, acc[2]);
        acc[3] = fmaf(hv, wa.w, acc[3]);
        acc[4] = fmaf(hv, wb.x, acc[4]);
        acc[5] = fmaf(hv, wb.y, acc[5]);
        acc[6] = fmaf(hv, wb.z, acc[6]);
        acc[7] = fmaf(hv, wb.w, acc[7]);
    }
    #pragma unroll
    for (int k = 0; k < 8; k++) sred[w][e][k] = acc[k];
    __syncthreads();

    int re = t >> 3, rk = t & 7;
    float s = 0.f;
    #pragma unroll
    for (int ww = 0; ww < 8; ww++) s += sred[ww][re][rk];
    int ridx = blockIdx.x*32 + re;
    if (ridx <= TABN + 2) {
        float v = (ridx == TABN + 2) ? 0.f : s + b2[rk];
        out[(size_t)ridx*8 + rk] = v;
    }
}

// ---------------- 32x64-tile fp32 GEMM, 128 threads, 4x4/thread -----------
// CTA-level split-K via blockIdx.z; with FLAG_RAW partials to C + z*M*ldc.
__global__ void __launch_bounds__(128) gemm_kernel(
        const float* __restrict__ A, int lda,
        const float* __restrict__ B, int ldb,
        const float* __restrict__ bias,
        float* __restrict__ C, int ldc,
        int M, int N, int K, int flags) {
    __shared__ __align__(16) float As[2][16][36];
    __shared__ __align__(16) float Bs[2][16][68];
    int t  = threadIdx.x;
    int m0 = blockIdx.y << 5, n0 = blockIdx.x << 6;
    int zi = blockIdx.z;
    const float* Az = A + (size_t)zi*K;
    const float* Bz = B + (size_t)zi*K*ldb;
    float* Cz = C + (size_t)zi*M*ldc;
    int arow = t >> 2, acol = (t & 3) << 2;
    int brow = t >> 3, bcol = (t & 7) << 3;
    int tx = t & 15, ty = t >> 4;
    float acc[4][4] = {};

    bool aval = (m0 + arow) < M;
    const float* Aptr = Az + (size_t)(m0 + arow)*lda + acol;
    const float* Bptr = Bz + (size_t)brow*ldb + n0 + bcol;

    float4 ra  = aval ? *(const float4*)Aptr : make_float4(0.f,0.f,0.f,0.f);
    float4 rb0 = *(const float4*)Bptr;
    float4 rb1 = *(const float4*)(Bptr + 4);
    int buf = 0;
    As[0][acol  ][arow] = ra.x; As[0][acol+1][arow] = ra.y;
    As[0][acol+2][arow] = ra.z; As[0][acol+3][arow] = ra.w;
    *(float4*)&Bs[0][brow][bcol]   = rb0;
    *(float4*)&Bs[0][brow][bcol+4] = rb1;
    __syncthreads();

    for (int k0 = 16; ; k0 += 16) {
        bool more = (k0 < K);
        if (more) {
            ra  = aval ? *(const float4*)(Aptr + k0) : make_float4(0.f,0.f,0.f,0.f);
            rb0 = *(const float4*)(Bptr + (size_t)k0*ldb);
            rb1 = *(const float4*)(Bptr + (size_t)k0*ldb + 4);
        }
        #pragma unroll
        for (int k = 0; k < 16; k++) {
            float4 a = *(const float4*)&As[buf][k][ty<<2];
            float4 b = *(const float4*)&Bs[buf][k][tx<<2];
            acc[0][0] = fmaf(a.x, b.x, acc[0][0]);
            acc[0][1] = fmaf(a.x, b.y, acc[0][1]);
            acc[0][2] = fmaf(a.x, b.z, acc[0][2]);
            acc[0][3] = fmaf(a.x, b.w, acc[0][3]);
            acc[1][0] = fmaf(a.y, b.x, acc[1][0]);
            acc[1][1] = fmaf(a.y, b.y, acc[1][1]);
            acc[1][2] = fmaf(a.y, b.z, acc[1][2]);
            acc[1][3] = fmaf(a.y, b.w, acc[1][3]);
            acc[2][0] = fmaf(a.z, b.x, acc[2][0]);
            acc[2][1] = fmaf(a.z, b.y, acc[2][1]);
            acc[2][2] = fmaf(a.z, b.z, acc[2][2]);
            acc[2][3] = fmaf(a.z, b.w, acc[2][3]);
            acc[3][0] = fmaf(a.w, b.x, acc[3][0]);
            acc[3][1] = fmaf(a.w, b.y, acc[3][1]);
            acc[3][2] = fmaf(a.w, b.z, acc[3][2]);
            acc[3][3] = fmaf(a.w, b.w, acc[3][3]);
        }
        if (!more) break;
        buf ^= 1;
        As[buf][acol  ][arow] = ra.x; As[buf][acol+1][arow] = ra.y;
        As[buf][acol+2][arow] = ra.z; As[buf][acol+3][arow] = ra.w;
        *(float4*)&Bs[buf][brow][bcol]   = rb0;
        *(float4*)&Bs[buf][brow][bcol+4] = rb1;
        __syncthreads();
    }

    if (flags & FLAG_RAW) {
        #pragma unroll
        for (int i = 0; i < 4; i++) {
            int m = m0 + (ty<<2) + i;
            if (m >= M) break;
            *(float4*)(Cz + (size_t)m*ldc + n0 + (tx<<2)) =
                make_float4(acc[i][0], acc[i][1], acc[i][2], acc[i][3]);
        }
        return;
    }
    float4 bv = *(const float4*)(bias + n0 + (tx<<2));
    #pragma unroll
    for (int i = 0; i < 4; i++) {
        int m = m0 + (ty<<2) + i;
        if (m >= M) break;
        float4 v = make_float4(acc[i][0]+bv.x, acc[i][1]+bv.y,
                               acc[i][2]+bv.z, acc[i][3]+bv.w);
        if (flags & FLAG_RELU) {
            v.x = fmaxf(v.x,0.f); v.y = fmaxf(v.y,0.f);
            v.z = fmaxf(v.z,0.f); v.w = fmaxf(v.w,0.f);
        }
        float4* cp = (float4*)(C + (size_t)m*ldc + n0 + (tx<<2));
        if (flags & FLAG_ADD) {
            float4 o = *cp;
            v.x += o.x; v.y += o.y; v.z += o.z; v.w += o.w;
        }
        *cp = v;
    }
}

// ---------------- split-K reduce: C = op(sum_s part[s] + bias) ------------
__global__ void __launch_bounds__(256) reduce_kernel(
        const float* __restrict__ part, const float* __restrict__ bias,
        float* __restrict__ C, int MN, int N, int S, int flags) {
    int idx = (blockIdx.x*256 + threadIdx.x) << 2;
    if (idx >= MN) return;
    float4 v = *(const float4*)(part + idx);
    for (int s = 1; s < S; s++) {
        float4 p = *(const float4*)(part + (size_t)s*MN + idx);
        v.x += p.x; v.y += p.y; v.z += p.z; v.w += p.w;
    }
    float4 bv = *(const float4*)(bias + (idx % N));
    v.x += bv.x; v.y += bv.y; v.z += bv.z; v.w += bv.w;
    if (flags & FLAG_RELU) {
        v.x = fmaxf(v.x,0.f); v.y = fmaxf(v.y,0.f);
        v.z = fmaxf(v.z,0.f); v.w = fmaxf(v.w,0.f);
    }
    float4* cp = (float4*)(C + idx);
    if (flags & FLAG_ADD) {
        float4 o = *cp;
        v.x += o.x; v.y += o.y; v.z += o.z; v.w += o.w;
    }
    *cp = v;
}

// ---------------- fused split-K reduce + residual + LayerNorm -------------
// mode 0 (fc1): rows 1..400 = sum(part rows 0..399)+bias, relu; row 0 = cls.
// mode 1 (proj): rows 0..400 = sum(part)+bias+h (residual add).
// Writes h and ln_out (LN with g/b) in one pass. One block per row.
__global__ void __launch_bounds__(256) reduce_ln_kernel(
        const float* __restrict__ part, const float* __restrict__ bias,
        const float* __restrict__ cls,
        float* __restrict__ h, float* __restrict__ ln_out,
        const float* __restrict__ g, const float* __restrict__ b,
        int S, int mode) {
    int row = blockIdx.x;          // 0..400
    int t = threadIdx.x;           // 256
    float v0, v1;
    if (mode == 0) {
        if (row == 0) {
            v0 = cls[t]; v1 = cls[t+256];
        } else {
            size_t base = (size_t)(row-1)*DIMM;
            size_t MN = (size_t)NPT*DIMM;
            v0 = 0.f; v1 = 0.f;
            for (int s = 0; s < S; s++) {
                v0 += part[(size_t)s*MN + base + t];
                v1 += part[(size_t)s*MN + base + t + 256];
            }
            v0 = fmaxf(v0 + bias[t],     0.f);
            v1 = fmaxf(v1 + bias[t+256], 0.f);
        }
        h[(size_t)row*DIMM + t]       = v0;
        h[(size_t)row*DIMM + t + 256] = v1;
    } else {
        size_t base = (size_t)row*DIMM;
        size_t MN = (size_t)NTOK*DIMM;
        v0 = 0.f; v1 = 0.f;
        for (int s = 0; s < S; s++) {
            v0 += part[(size_t)s*MN + base + t];
            v1 += part[(size_t)s*MN + base + t + 256];
        }
        v0 += bias[t]     + h[base + t];
        v1 += bias[t+256] + h[base + t + 256];
        h[base + t]       = v0;
        h[base + t + 256] = v1;
    }
    float2 sr = blockReduce2_256(v0+v1, v0*v0+v1*v1);
    float mean = sr.x * (1.f/512.f);
    float inv  = rsqrtf(sr.y*(1.f/512.f) - mean*mean + 1e-5f);
    ln_out[(size_t)row*DIMM + t]       = (v0-mean)*inv*g[t]     + b[t];
    ln_out[(size_t)row*DIMM + t + 256] = (v1-mean)*inv*g[t+256] + b[t+256];
}

// ---------------- QK^T scores + fused CPB bias ----------------
__global__ void __launch_bounds__(128) scores_kernel(const float* __restrict__ tab) {
    __shared__ __align__(16) float Qs[64][36];   // [d][i]
    __shared__ __align__(16) float Ks[64][68];   // [d][j]
    int h  = blockIdx.z;
    int i0 = blockIdx.y << 5, j0 = blockIdx.x << 6;
    int t  = threadIdx.x;

    {
        int r = t >> 2, c = (t & 3) << 4;
        const float* qp = g_qkv + (size_t)(i0+r)*QKV3 + h*HDIM + c;
        bool v = (i0 + r) < NTOK;
        #pragma unroll
        for (int q = 0; q < 4; q++) {
            float4 x = v ? *(const float4*)(qp + (q<<2)) : make_float4(0.f,0.f,0.f,0.f);
            int d = c + (q<<2);
            Qs[d  ][r] = x.x; Qs[d+1][r] = x.y;
            Qs[d+2][r] = x.z; Qs[d+3][r] = x.w;
        }
    }
    {
        int r = t >> 1, c = (t & 1) << 5;
        const float* kp = g_qkv + (size_t)(j0+r)*QKV3 + DIMM + h*HDIM + c;
        bool v = (j0 + r) < NTOK;
        #pragma unroll
        for (int q = 0; q < 8; q++) {
            float4 x = v ? *(const float4*)(kp + (q<<2)) : make_float4(0.f,0.f,0.f,0.f);
            int d = c + (q<<2);
            Ks[d  ][r] = x.x; Ks[d+1][r] = x.y;
            Ks[d+2][r] = x.z; Ks[d+3][r] = x.w;
        }
    }
    __syncthreads();

    int tx = t & 15, ty = t >> 4;
    float acc[4][4] = {};
    #pragma unroll 8
    for (int d = 0; d < 64; d++) {
        float4 a = *(const float4*)&Qs[d][ty<<2];
        float4 b = *(const float4*)&Ks[d][tx<<2];
        acc[0][0] = fmaf(a.x, b.x, acc[0][0]);
        acc[0][1] = fmaf(a.x, b.y, acc[0][1]);
        acc[0][2] = fmaf(a.x, b.z, acc[0][2]);
        acc[0][3] = fmaf(a.x, b.w, acc[0][3]);
        acc[1][0] = fmaf(a.y, b.x, acc[1][0]);
        acc[1][1] = fmaf(a.y, b.y, acc[1][1]);
        acc[1][2] = fmaf(a.y, b.z, acc[1][2]);
        acc[1][3] = fmaf(a.y, b.w, acc[1][3]);
        acc[2][0] = fmaf(a.z, b.x, acc[2][0]);
        acc[2][1] = fmaf(a.z, b.y, acc[2][1]);
        acc[2][2] = fmaf(a.z, b.z, acc[2][2]);
        acc[2][3] = fmaf(a.z, b.w, acc[2][3]);
        acc[3][0] = fmaf(a.w, b.x, acc[3][0]);
        acc[3][1] = fmaf(a.w, b.y, acc[3][1]);
        acc[3][2] = fmaf(a.w, b.z, acc[3][2]);
        acc[3][3] = fmaf(a.w, b.w, acc[3][3]);
    }

    #pragma unroll
    for (int qi = 0; qi < 4; qi++) {
        int i = i0 + (ty<<2) + qi;
        if (i >= NTOK) break;
        #pragma unroll
        for (int qj = 0; qj < 4; qj++) {
            int j = j0 + (tx<<2) + qj;
            if (j < NTOK) {
                size_t p = (size_t)i*NTOK + j;
                float pos = g_angpos[p];
                int   ip  = (int)pos;
                float f   = pos - (float)ip;
                const float* r0 = tab + (size_t)ip*8 + h;
                float bias = r0[0] + f*(r0[8] - r0[0]);
                g_attn[(size_t)h*NTOK*NTOK + p] = fmaf(0.125f, acc[qi][qj], bias);
            }
        }
    }
}

// ---------------- fused softmax + attn@V (per-head, 32 i-rows) ------------
__global__ void __launch_bounds__(256) softav_kernel() {
    __shared__ float sa[32][33];
    __shared__ __align__(16) float sv[32][68];
    __shared__ float smx[32], sinv[32];
    int h  = blockIdx.y;
    int i0 = blockIdx.x << 5;
    int t  = threadIdx.x;

    {
        int row = t >> 3, k8 = t & 7;
        int gi  = i0 + row;
        int cgi = gi < NTOK ? gi : NTOK - 1;
        const float* arow = g_attn + ((size_t)h*NTOK + cgi)*NTOK;
        float m = -1e30f;
        for (int j = k8; j < NTOK; j += 8) m = fmaxf(m, arow[j]);
        #pragma unroll
        for (int o = 1; o < 8; o <<= 1)
            m = fmaxf(m, __shfl_xor_sync(0xffffffffu, m, o));
        float s = 0.f;
        for (int j = k8; j < NTOK; j += 8) s += __expf(arow[j] - m);
        #pragma unroll
        for (int o = 1; o < 8; o <<= 1)
            s += __shfl_xor_sync(0xffffffffu, s, o);
        if (k8 == 0) { smx[row] = m; sinv[row] = 1.f / s; }
    }
    __syncthreads();

    int tx = t & 15, ty = t >> 4;
    int d4 = tx << 2;
    int ar = t >> 3, ac = (t & 7) << 2;
    int vr = t >> 3, vc = (t & 7) << 3;
    float mrow = smx[ar];
    float acc[2][4] = {};
    for (int j0 = 0; j0 < NTOK; j0 += 32) {
        #pragma unroll
        for (int q = 0; q < 4; q++) {
            int i = i0 + ar, j = j0 + ac + q;
            float e = 0.f;
            if (i < NTOK && j < NTOK)
                e = __expf(g_attn[((size_t)h*NTOK + i)*NTOK + j] - mrow);
            sa[ar][ac+q] = e;
        }
        {
            const float* vp = g_qkv + (size_t)(j0+vr)*QKV3 + 2*DIMM + h*HDIM + vc;
            bool vi = (j0 + vr < NTOK);
            float4 z = make_float4(0.f,0.f,0.f,0.f);
            float4 v0 = vi ? *(const float4*)vp       : z;
            float4 v1 = vi ? *(const float4*)(vp + 4) : z;
            *(float4*)&sv[vr][vc]   = v0;
            *(float4*)&sv[vr][vc+4] = v1;
        }
        __syncthreads();
        #pragma unroll
        for (int j = 0; j < 32; j++) {
            float4 vv = *(const float4*)&sv[j][d4];
            float a0 = sa[ty][j], a1 = sa[ty+16][j];
            acc[0][0] = fmaf(a0, vv.x, acc[0][0]);
            acc[0][1] = fmaf(a0, vv.y, acc[0][1]);
            acc[0][2] = fmaf(a0, vv.z, acc[0][2]);
            acc[0][3] = fmaf(a0, vv.w, acc[0][3]);
            acc[1][0] = fmaf(a1, vv.x, acc[1][0]);
            acc[1][1] = fmaf(a1, vv.y, acc[1][1]);
            acc[1][2] = fmaf(a1, vv.z, acc[1][2]);
            acc[1][3] = fmaf(a1, vv.w, acc[1][3]);
        }
        __syncthreads();
    }
    #pragma unroll
    for (int q = 0; q < 2; q++) {
        int i = i0 + ty + (q<<4);
        if (i < NTOK) {
            float inv = sinv[ty + (q<<4)];
            *(float4*)(g_ao + (size_t)i*DIMM + h*HDIM + d4) =
                make_float4(acc[q][0]*inv, acc[q][1]*inv,
                            acc[q][2]*inv, acc[q][3]*inv);
        }
    }
}

// ---------------- final: LN(row 0) -> fc2 -> out[2] ----------------
__global__ void final_kernel(const float* __restrict__ g, const float* __restrict__ b,
                             const float* __restrict__ w, const float* __restrict__ bias,
                             float* __restrict__ out) {
    int t = threadIdx.x;                  // 256 threads
    float v0 = g_h[t], v1 = g_h[t+256];
    float2 s = blockReduce2_256(v0+v1, v0*v0+v1*v1);
    float mean = s.x * (1.f/512.f);
    float inv  = rsqrtf(s.y*(1.f/512.f) - mean*mean + 1e-5f);
    float l0 = (v0-mean)*inv*g[t]     + b[t];
    float l1 = (v1-mean)*inv*g[t+256] + b[t+256];
    float p0 = l0*w[t*2]   + l1*w[(t+256)*2];
    float p1 = l0*w[t*2+1] + l1*w[(t+256)*2+1];
    float2 sp = blockReduce2_256(p0, p1);
    if (t == 0) { out[0] = sp.x + bias[0]; out[1] = sp.y + bias[1]; }
}

// ---------------- launch ----------------
extern "C" void kernel_launch(void* const* d_in, const int* in_sizes, int n_in,
                              void* d_out, int out_size) {
    const float* h_in   = (const float*)d_in[0];
    const float* coords = (const float*)d_in[1];
    const float* fc1_w  = (const float*)d_in[2];
    const float* fc1_b  = (const float*)d_in[3];
    const float* cls    = (const float*)d_in[4];
    const float* norm_g = (const float*)d_in[25];
    const float* norm_b = (const float*)d_in[26];
    const float* fc2_w  = (const float*)d_in[27];
    const float* fc2_b  = (const float*)d_in[28];
    const float* l1_ln_g = (const float*)d_in[5];
    const float* l1_ln_b = (const float*)d_in[6];
    const float* l2_ln_g = (const float*)d_in[15];
    const float* l2_ln_b = (const float*)d_in[16];

    float *p_h, *p_ln, *p_qkv, *p_ao, *p_part, *p_tab[2];
    cudaGetSymbolAddress((void**)&p_h,      g_h);
    cudaGetSymbolAddress((void**)&p_ln,     g_ln);
    cudaGetSymbolAddress((void**)&p_qkv,    g_qkv);
    cudaGetSymbolAddress((void**)&p_ao,     g_ao);
    cudaGetSymbolAddress((void**)&p_part,   g_part);
    cudaGetSymbolAddress((void**)&p_tab[0], g_table0);
    cudaGetSymbolAddress((void**)&p_tab[1], g_table1);

    angpos_kernel<<<(NPAIR + 255)/256, 256>>>(coords);
    cpb_table_kernel<<<dim3((TABN + 3 + 31)/32, 2), 256>>>(
        (const float*)d_in[7],  (const float*)d_in[8],
        (const float*)d_in[9],  (const float*)d_in[10], p_tab[0],
        (const float*)d_in[17], (const float*)d_in[18],
        (const float*)d_in[19], (const float*)d_in[20], p_tab[1]);

    // fc1: split-K x8 (K=1024 -> 8x128); fused reduce+relu+CLS+LN(L1)
    gemm_kernel<<<dim3(DIMM/64, (NPT+31)/32, 8), 128>>>(
        h_in, 1024, fc1_w, DIMM, (const float*)0,
        p_part, DIMM, NPT, DIMM, 128, FLAG_RAW);
    reduce_ln_kernel<<<NTOK, 256>>>(
        p_part, fc1_b, cls, p_h, p_ln, l1_ln_g, l1_ln_b, 8, 0);

    for (int L = 0; L < 2; L++) {
        const float* lp[10];
        for (int q = 0; q < 10; q++) lp[q] = (const float*)d_in[5 + L*10 + q];
        const float* qkv_w  = lp[6]; const float* qkv_b  = lp[7];
        const float* proj_w = lp[8]; const float* proj_b = lp[9];

        // qkv: split-K x2 (K=512 -> 2x256), reduce+bias
        gemm_kernel<<<dim3(QKV3/64, (NTOK+31)/32, 2), 128>>>(
            p_ln, DIMM, qkv_w, QKV3, (const float*)0,
            p_part, QKV3, NTOK, QKV3, 256, FLAG_RAW);
        reduce_kernel<<<(NTOK*QKV3/4 + 255)/256, 256>>>(
            p_part, qkv_b, p_qkv, NTOK*QKV3, QKV3, 2, 0);
        scores_kernel<<<dim3(7, 13, NHEAD), 128>>>(p_tab[L]);
        softav_kernel<<<dim3(13, NHEAD), 256>>>();
        // proj: split-K x4 (K=512 -> 4x128)
        gemm_kernel<<<dim3(DIMM/64, (NTOK+31)/32, 4), 128>>>(
            p_ao, DIMM, proj_w, DIMM, (const float*)0,
            p_part, DIMM, NTOK, DIMM, 128, FLAG_RAW);
        if (L == 0) {
            // fused reduce+residual+LN(L2)
            reduce_ln_kernel<<<NTOK, 256>>>(
                p_part, proj_b, cls, p_h, p_ln, l2_ln_g, l2_ln_b, 4, 1);
        } else {
            reduce_kernel<<<(NTOK*DIMM/4 + 255)/256, 256>>>(
                p_part, proj_b, p_h, NTOK*DIMM, DIMM, 4, FLAG_ADD);
        }
    }

    final_kernel<<<1, 256>>>(norm_g, norm_b, fc2_w, fc2_b, (float*)d_out);
}

// round 15
// speedup vs baseline: 1.2519x; 1.1516x over previous
#include <cuda_runtime.h>
#include <math.h>

#define NTOK 401
#define NPT  400
#define DIMM 512
#define NHEAD 8
#define HDIM 64
#define QKV3 1536
#define CPBH 512
#define NPAIR (NTOK*NTOK)
#define TABN 4096
#define PI_F 3.14159265358979323846f
#define FLAG_RELU 1
#define FLAG_ADD  2
#define FLAG_RAW  4

// ---------------- scratch (alloc-free, __device__ globals) ----------------
__device__ float  g_h[NTOK*DIMM];          // residual stream
__device__ float  g_ln[NTOK*DIMM];         // layernorm output
__device__ float  g_qkv[NTOK*QKV3];        // fused qkv (layer 1)
__device__ float  g_kv[NTOK*1024];         // K,V only (layer 2)
__device__ float  g_q0[DIMM];              // Q row 0 (layer 2)
__device__ float  g_attn[NHEAD*NTOK*NTOK]; // attention logits (L1, 5.1 MB)
__device__ float  g_ao[NTOK*DIMM];         // attention output (pre-proj)
__device__ float  g_part[8*NTOK*DIMM];     // split-K partials (6.6 MB)
__device__ float  g_angpos[NPAIR];         // table position per pair (both layers)
__device__ float  g_table0[(TABN+4)*8];    // layer-1 bias table
__device__ float  g_table1[(TABN+4)*8];    // layer-2 bias table

// ---------------- small helpers ----------------
__device__ __forceinline__ float2 blockReduce2_256(float a, float b) {
    __shared__ float sa[8], sb[8];
    __syncthreads();
    #pragma unroll
    for (int o = 16; o > 0; o >>= 1) {
        a += __shfl_xor_sync(0xffffffffu, a, o);
        b += __shfl_xor_sync(0xffffffffu, b, o);
    }
    int w = threadIdx.x >> 5;
    if ((threadIdx.x & 31) == 0) { sa[w] = a; sb[w] = b; }
    __syncthreads();
    a = sa[0]+sa[1]+sa[2]+sa[3]+sa[4]+sa[5]+sa[6]+sa[7];
    b = sb[0]+sb[1]+sb[2]+sb[3]+sb[4]+sb[5]+sb[6]+sb[7];
    return make_float2(a, b);
}

// ---------------- per-pair angle table position (symmetry: compute i<j) ---
// token 0 = CLS at origin; token i>=1 uses coords[i-1].
__global__ void angpos_kernel(const float* __restrict__ coords) {
    int p = blockIdx.x*blockDim.x + threadIdx.x;
    if (p >= NPAIR) return;
    int i = p / NTOK, j = p - i*NTOK;
    if (i > j) return;
    if (i == j) { g_angpos[p] = (float)(TABN + 1); return; }
    float xi = (i == 0) ? 0.f : coords[2*(i-1)];
    float yi = (i == 0) ? 0.f : coords[2*(i-1)+1];
    float xj = coords[2*(j-1)];
    float yj = coords[2*(j-1)+1];
    float th = atan2f(yi - yj, xi - xj);
    float pos = (th + PI_F) * ((float)TABN / (2.0f*PI_F));
    pos = fminf(fmaxf(pos, 0.f), (float)TABN);
    g_angpos[p] = pos;
    // opposite direction: theta + pi  <=>  pos +- TABN/2 (table is periodic)
    float pos2 = pos + ((pos < (float)(TABN/2)) ? (float)(TABN/2) : -(float)(TABN/2));
    g_angpos[(size_t)j*NTOK + i] = pos2;
}

// ---------------- build CPB bias tables (both layers, grid.y selects) ----
__global__ void __launch_bounds__(256) cpb_table_kernel(
        const float* __restrict__ w1a, const float* __restrict__ b1a,
        const float* __restrict__ w2a, const float* __restrict__ b2a,
        float* __restrict__ outa,
        const float* __restrict__ w1b, const float* __restrict__ b1b,
        const float* __restrict__ w2b, const float* __restrict__ b2b,
        float* __restrict__ outb) {
    const float* w1 = blockIdx.y ? w1b : w1a;
    const float* b1 = blockIdx.y ? b1b : b1a;
    const float* w2 = blockIdx.y ? w2b : w2a;
    const float* b2 = blockIdx.y ? b2b : b2a;
    float*      out = blockIdx.y ? outb : outa;

    __shared__ float swx[CPBH], swy[CPBH], sbb[CPBH];
    __shared__ __align__(16) float sw2[CPBH*8];
    __shared__ float sred[8][32][9];
    int t = threadIdx.x;
    for (int c = t; c < CPBH; c += 256) {
        swx[c] = w1[c]; swy[c] = w1[CPBH + c]; sbb[c] = b1[c];
    }
    for (int c = t; c < CPBH*2; c += 256)
        *(float4*)(sw2 + c*4) = *(const float4*)(w2 + c*4);
    __syncthreads();

    int e = t & 31;
    int w = t >> 5;
    int idx = blockIdx.x*32 + e;
    float ux = 0.f, uy = 0.f;
    if (idx <= TABN) {
        float th = -PI_F + (2.0f*PI_F) * ((float)idx / (float)TABN);
        sincosf(th, &uy, &ux);
    }
    float acc[8] = {0.f,0.f,0.f,0.f,0.f,0.f,0.f,0.f};
    int c0 = w << 6;
    #pragma unroll 8
    for (int cc = 0; cc < 64; cc++) {
        int c = c0 + cc;
        float hv = fmaf(ux, swx[c], fmaf(uy, swy[c], sbb[c]));
        hv = fmaxf(hv, 0.f);
        float4 wa = *(const float4*)(sw2 + (c<<3));
        float4 wb = *(const float4*)(sw2 + (c<<3) + 4);
        acc[0] = fmaf(hv, wa.x, acc[0]);
        acc[1] = fmaf(hv, wa.y, acc[1]);
        acc[2] = fmaf(hv, wa.z, acc[2]);
        acc[3] = fmaf(hv, wa.w, acc[3]);
        acc[4] = fmaf(hv, wb.x, acc[4]);
        acc[5] = fmaf(hv, wb.y, acc[5]);
        acc[6] = fmaf(hv, wb.z, acc[6]);
        acc[7] = fmaf(hv, wb.w, acc[7]);
    }
    #pragma unroll
    for (int k = 0; k < 8; k++) sred[w][e][k] = acc[k];
    __syncthreads();

    int re = t >> 3, rk = t & 7;
    float s = 0.f;
    #pragma unroll
    for (int ww = 0; ww < 8; ww++) s += sred[ww][re][rk];
    int ridx = blockIdx.x*32 + re;
    if (ridx <= TABN + 2) {
        float v = (ridx == TABN + 2) ? 0.f : s + b2[rk];
        out[(size_t)ridx*8 + rk] = v;
    }
}

// ---------------- 32x64-tile fp32 GEMM, 128 threads, 4x4/thread -----------
// CTA-level split-K via blockIdx.z; with FLAG_RAW partials to C + z*M*ldc.
__global__ void __launch_bounds__(128) gemm_kernel(
        const float* __restrict__ A, int lda,
        const float* __restrict__ B, int ldb,
        const float* __restrict__ bias,
        float* __restrict__ C, int ldc,
        int M, int N, int K, int flags) {
    __shared__ __align__(16) float As[2][16][36];
    __shared__ __align__(16) float Bs[2][16][68];
    int t  = threadIdx.x;
    int m0 = blockIdx.y << 5, n0 = blockIdx.x << 6;
    int zi = blockIdx.z;
    const float* Az = A + (size_t)zi*K;
    const float* Bz = B + (size_t)zi*K*ldb;
    float* Cz = C + (size_t)zi*M*ldc;
    int arow = t >> 2, acol = (t & 3) << 2;
    int brow = t >> 3, bcol = (t & 7) << 3;
    int tx = t & 15, ty = t >> 4;
    float acc[4][4] = {};

    bool aval = (m0 + arow) < M;
    const float* Aptr = Az + (size_t)(m0 + arow)*lda + acol;
    const float* Bptr = Bz + (size_t)brow*ldb + n0 + bcol;

    float4 ra  = aval ? *(const float4*)Aptr : make_float4(0.f,0.f,0.f,0.f);
    float4 rb0 = *(const float4*)Bptr;
    float4 rb1 = *(const float4*)(Bptr + 4);
    int buf = 0;
    As[0][acol  ][arow] = ra.x; As[0][acol+1][arow] = ra.y;
    As[0][acol+2][arow] = ra.z; As[0][acol+3][arow] = ra.w;
    *(float4*)&Bs[0][brow][bcol]   = rb0;
    *(float4*)&Bs[0][brow][bcol+4] = rb1;
    __syncthreads();

    for (int k0 = 16; ; k0 += 16) {
        bool more = (k0 < K);
        if (more) {
            ra  = aval ? *(const float4*)(Aptr + k0) : make_float4(0.f,0.f,0.f,0.f);
            rb0 = *(const float4*)(Bptr + (size_t)k0*ldb);
            rb1 = *(const float4*)(Bptr + (size_t)k0*ldb + 4);
        }
        #pragma unroll
        for (int k = 0; k < 16; k++) {
            float4 a = *(const float4*)&As[buf][k][ty<<2];
            float4 b = *(const float4*)&Bs[buf][k][tx<<2];
            acc[0][0] = fmaf(a.x, b.x, acc[0][0]);
            acc[0][1] = fmaf(a.x, b.y, acc[0][1]);
            acc[0][2] = fmaf(a.x, b.z, acc[0][2]);
            acc[0][3] = fmaf(a.x, b.w, acc[0][3]);
            acc[1][0] = fmaf(a.y, b.x, acc[1][0]);
            acc[1][1] = fmaf(a.y, b.y, acc[1][1]);
            acc[1][2] = fmaf(a.y, b.z, acc[1][2]);
            acc[1][3] = fmaf(a.y, b.w, acc[1][3]);
            acc[2][0] = fmaf(a.z, b.x, acc[2][0]);
            acc[2][1] = fmaf(a.z, b.y, acc[2][1]);
            acc[2][2] = fmaf(a.z, b.z, acc[2][2]);
            acc[2][3] = fmaf(a.z, b.w, acc[2][3]);
            acc[3][0] = fmaf(a.w, b.x, acc[3][0]);
            acc[3][1] = fmaf(a.w, b.y, acc[3][1]);
            acc[3][2] = fmaf(a.w, b.z, acc[3][2]);
            acc[3][3] = fmaf(a.w, b.w, acc[3][3]);
        }
        if (!more) break;
        buf ^= 1;
        As[buf][acol  ][arow] = ra.x; As[buf][acol+1][arow] = ra.y;
        As[buf][acol+2][arow] = ra.z; As[buf][acol+3][arow] = ra.w;
        *(float4*)&Bs[buf][brow][bcol]   = rb0;
        *(float4*)&Bs[buf][brow][bcol+4] = rb1;
        __syncthreads();
    }

    if (flags & FLAG_RAW) {
        #pragma unroll
        for (int i = 0; i < 4; i++) {
            int m = m0 + (ty<<2) + i;
            if (m >= M) break;
            *(float4*)(Cz + (size_t)m*ldc + n0 + (tx<<2)) =
                make_float4(acc[i][0], acc[i][1], acc[i][2], acc[i][3]);
        }
        return;
    }
    float4 bv = *(const float4*)(bias + n0 + (tx<<2));
    #pragma unroll
    for (int i = 0; i < 4; i++) {
        int m = m0 + (ty<<2) + i;
        if (m >= M) break;
        float4 v = make_float4(acc[i][0]+bv.x, acc[i][1]+bv.y,
                               acc[i][2]+bv.z, acc[i][3]+bv.w);
        if (flags & FLAG_RELU) {
            v.x = fmaxf(v.x,0.f); v.y = fmaxf(v.y,0.f);
            v.z = fmaxf(v.z,0.f); v.w = fmaxf(v.w,0.f);
        }
        float4* cp = (float4*)(C + (size_t)m*ldc + n0 + (tx<<2));
        if (flags & FLAG_ADD) {
            float4 o = *cp;
            v.x += o.x; v.y += o.y; v.z += o.z; v.w += o.w;
        }
        *cp = v;
    }
}

// ---------------- split-K reduce: C = op(sum_s part[s] + bias) ------------
__global__ void __launch_bounds__(256) reduce_kernel(
        const float* __restrict__ part, const float* __restrict__ bias,
        float* __restrict__ C, int MN, int N, int S, int flags) {
    int idx = (blockIdx.x*256 + threadIdx.x) << 2;
    if (idx >= MN) return;
    float4 v = *(const float4*)(part + idx);
    for (int s = 1; s < S; s++) {
        float4 p = *(const float4*)(part + (size_t)s*MN + idx);
        v.x += p.x; v.y += p.y; v.z += p.z; v.w += p.w;
    }
    float4 bv = *(const float4*)(bias + (idx % N));
    v.x += bv.x; v.y += bv.y; v.z += bv.z; v.w += bv.w;
    if (flags & FLAG_RELU) {
        v.x = fmaxf(v.x,0.f); v.y = fmaxf(v.y,0.f);
        v.z = fmaxf(v.z,0.f); v.w = fmaxf(v.w,0.f);
    }
    float4* cp = (float4*)(C + idx);
    if (flags & FLAG_ADD) {
        float4 o = *cp;
        v.x += o.x; v.y += o.y; v.z += o.z; v.w += o.w;
    }
    *cp = v;
}

// ---------------- fused split-K reduce + residual + LayerNorm -------------
__global__ void __launch_bounds__(256) reduce_ln_kernel(
        const float* __restrict__ part, const float* __restrict__ bias,
        const float* __restrict__ cls,
        float* __restrict__ h, float* __restrict__ ln_out,
        const float* __restrict__ g, const float* __restrict__ b,
        int S, int mode) {
    int row = blockIdx.x;          // 0..400
    int t = threadIdx.x;           // 256
    float v0, v1;
    if (mode == 0) {
        if (row == 0) {
            v0 = cls[t]; v1 = cls[t+256];
        } else {
            size_t base = (size_t)(row-1)*DIMM;
            size_t MN = (size_t)NPT*DIMM;
            v0 = 0.f; v1 = 0.f;
            for (int s = 0; s < S; s++) {
                v0 += part[(size_t)s*MN + base + t];
                v1 += part[(size_t)s*MN + base + t + 256];
            }
            v0 = fmaxf(v0 + bias[t],     0.f);
            v1 = fmaxf(v1 + bias[t+256], 0.f);
        }
        h[(size_t)row*DIMM + t]       = v0;
        h[(size_t)row*DIMM + t + 256] = v1;
    } else {
        size_t base = (size_t)row*DIMM;
        size_t MN = (size_t)NTOK*DIMM;
        v0 = 0.f; v1 = 0.f;
        for (int s = 0; s < S; s++) {
            v0 += part[(size_t)s*MN + base + t];
            v1 += part[(size_t)s*MN + base + t + 256];
        }
        v0 += bias[t]     + h[base + t];
        v1 += bias[t+256] + h[base + t + 256];
        h[base + t]       = v0;
        h[base + t + 256] = v1;
    }
    float2 sr = blockReduce2_256(v0+v1, v0*v0+v1*v1);
    float mean = sr.x * (1.f/512.f);
    float inv  = rsqrtf(sr.y*(1.f/512.f) - mean*mean + 1e-5f);
    ln_out[(size_t)row*DIMM + t]       = (v0-mean)*inv*g[t]     + b[t];
    ln_out[(size_t)row*DIMM + t + 256] = (v1-mean)*inv*g[t+256] + b[t+256];
}

// ---------------- QK^T scores + fused CPB bias (layer 1) ----------------
__global__ void __launch_bounds__(128) scores_kernel(const float* __restrict__ tab) {
    __shared__ __align__(16) float Qs[64][36];   // [d][i]
    __shared__ __align__(16) float Ks[64][68];   // [d][j]
    int h  = blockIdx.z;
    int i0 = blockIdx.y << 5, j0 = blockIdx.x << 6;
    int t  = threadIdx.x;

    {
        int r = t >> 2, c = (t & 3) << 4;
        const float* qp = g_qkv + (size_t)(i0+r)*QKV3 + h*HDIM + c;
        bool v = (i0 + r) < NTOK;
        #pragma unroll
        for (int q = 0; q < 4; q++) {
            float4 x = v ? *(const float4*)(qp + (q<<2)) : make_float4(0.f,0.f,0.f,0.f);
            int d = c + (q<<2);
            Qs[d  ][r] = x.x; Qs[d+1][r] = x.y;
            Qs[d+2][r] = x.z; Qs[d+3][r] = x.w;
        }
    }
    {
        int r = t >> 1, c = (t & 1) << 5;
        const float* kp = g_qkv + (size_t)(j0+r)*QKV3 + DIMM + h*HDIM + c;
        bool v = (j0 + r) < NTOK;
        #pragma unroll
        for (int q = 0; q < 8; q++) {
            float4 x = v ? *(const float4*)(kp + (q<<2)) : make_float4(0.f,0.f,0.f,0.f);
            int d = c + (q<<2);
            Ks[d  ][r] = x.x; Ks[d+1][r] = x.y;
            Ks[d+2][r] = x.z; Ks[d+3][r] = x.w;
        }
    }
    __syncthreads();

    int tx = t & 15, ty = t >> 4;
    float acc[4][4] = {};
    #pragma unroll 8
    for (int d = 0; d < 64; d++) {
        float4 a = *(const float4*)&Qs[d][ty<<2];
        float4 b = *(const float4*)&Ks[d][tx<<2];
        acc[0][0] = fmaf(a.x, b.x, acc[0][0]);
        acc[0][1] = fmaf(a.x, b.y, acc[0][1]);
        acc[0][2] = fmaf(a.x, b.z, acc[0][2]);
        acc[0][3] = fmaf(a.x, b.w, acc[0][3]);
        acc[1][0] = fmaf(a.y, b.x, acc[1][0]);
        acc[1][1] = fmaf(a.y, b.y, acc[1][1]);
        acc[1][2] = fmaf(a.y, b.z, acc[1][2]);
        acc[1][3] = fmaf(a.y, b.w, acc[1][3]);
        acc[2][0] = fmaf(a.z, b.x, acc[2][0]);
        acc[2][1] = fmaf(a.z, b.y, acc[2][1]);
        acc[2][2] = fmaf(a.z, b.z, acc[2][2]);
        acc[2][3] = fmaf(a.z, b.w, acc[2][3]);
        acc[3][0] = fmaf(a.w, b.x, acc[3][0]);
        acc[3][1] = fmaf(a.w, b.y, acc[3][1]);
        acc[3][2] = fmaf(a.w, b.z, acc[3][2]);
        acc[3][3] = fmaf(a.w, b.w, acc[3][3]);
    }

    #pragma unroll
    for (int qi = 0; qi < 4; qi++) {
        int i = i0 + (ty<<2) + qi;
        if (i >= NTOK) break;
        #pragma unroll
        for (int qj = 0; qj < 4; qj++) {
            int j = j0 + (tx<<2) + qj;
            if (j < NTOK) {
                size_t p = (size_t)i*NTOK + j;
                float pos = g_angpos[p];
                int   ip  = (int)pos;
                float f   = pos - (float)ip;
                const float* r0 = tab + (size_t)ip*8 + h;
                float bias = r0[0] + f*(r0[8] - r0[0]);
                g_attn[(size_t)h*NTOK*NTOK + p] = fmaf(0.125f, acc[qi][qj], bias);
            }
        }
    }
}

// ---------------- fused softmax + attn@V (layer 1; 16 i-rows per CTA) -----
__global__ void __launch_bounds__(256) softav_kernel() {
    __shared__ float sa[16][33];
    __shared__ __align__(16) float sv[32][68];
    __shared__ float smx[16], sinv[16];
    int h  = blockIdx.y;
    int i0 = blockIdx.x << 4;
    int t  = threadIdx.x;

    {   // stats: 16 threads per row (shuffle groups of 16)
        int row = t >> 4, k = t & 15;
        int gi  = i0 + row;
        int cgi = gi < NTOK ? gi : NTOK - 1;
        const float* arow = g_attn + ((size_t)h*NTOK + cgi)*NTOK;
        float m = -1e30f;
        for (int j = k; j < NTOK; j += 16) m = fmaxf(m, arow[j]);
        #pragma unroll
        for (int o = 1; o < 16; o <<= 1)
            m = fmaxf(m, __shfl_xor_sync(0xffffffffu, m, o));
        float s = 0.f;
        for (int j = k; j < NTOK; j += 16) s += __expf(arow[j] - m);
        #pragma unroll
        for (int o = 1; o < 16; o <<= 1)
            s += __shfl_xor_sync(0xffffffffu, s, o);
        if (k == 0) { smx[row] = m; sinv[row] = 1.f / s; }
    }
    __syncthreads();

    int tx = t & 15, ty = t >> 4;         // ty: row 0..15, tx -> d4
    int d4 = tx << 2;
    int ar = t >> 4, ac = (t & 15) << 1;  // sa load: 2 j per thread
    int vr = t >> 3, vc = (t & 7) << 3;
    float mrow = smx[ar];
    float acc[4] = {0.f, 0.f, 0.f, 0.f};
    for (int j0 = 0; j0 < NTOK; j0 += 32) {
        #pragma unroll
        for (int q = 0; q < 2; q++) {
            int i = i0 + ar, j = j0 + ac + q;
            float e = 0.f;
            if (i < NTOK && j < NTOK)
                e = __expf(g_attn[((size_t)h*NTOK + i)*NTOK + j] - mrow);
            sa[ar][ac+q] = e;
        }
        {
            const float* vp = g_qkv + (size_t)(j0+vr)*QKV3 + 2*DIMM + h*HDIM + vc;
            bool vi = (j0 + vr < NTOK);
            float4 z = make_float4(0.f,0.f,0.f,0.f);
            float4 v0 = vi ? *(const float4*)vp       : z;
            float4 v1 = vi ? *(const float4*)(vp + 4) : z;
            *(float4*)&sv[vr][vc]   = v0;
            *(float4*)&sv[vr][vc+4] = v1;
        }
        __syncthreads();
        #pragma unroll
        for (int j = 0; j < 32; j++) {
            float4 vv = *(const float4*)&sv[j][d4];
            float a0 = sa[ty][j];
            acc[0] = fmaf(a0, vv.x, acc[0]);
            acc[1] = fmaf(a0, vv.y, acc[1]);
            acc[2] = fmaf(a0, vv.z, acc[2]);
            acc[3] = fmaf(a0, vv.w, acc[3]);
        }
        __syncthreads();
    }
    int i = i0 + ty;
    if (i < NTOK) {
        float inv = sinv[ty];
        *(float4*)(g_ao + (size_t)i*DIMM + h*HDIM + d4) =
            make_float4(acc[0]*inv, acc[1]*inv, acc[2]*inv, acc[3]*inv);
    }
}

// ---------------- L2: Q for row 0 only ----------------
__global__ void __launch_bounds__(256) q0_kernel(
        const float* __restrict__ w, const float* __restrict__ b) {
    __shared__ float s0[DIMM];
    int t = threadIdx.x;
    int n = blockIdx.x*256 + t;
    for (int c = t; c < DIMM; c += 256) s0[c] = g_ln[c];
    __syncthreads();
    float acc = b[n];
    #pragma unroll 8
    for (int c = 0; c < DIMM; c++)
        acc = fmaf(s0[c], w[(size_t)c*QKV3 + n], acc);
    g_q0[n] = acc;
}

// ---------------- L2: attention for row 0 (one CTA per head) --------------
__global__ void __launch_bounds__(256) attn_row_kernel(const float* __restrict__ tab) {
    __shared__ float sq[64];
    __shared__ float sj[NTOK];
    __shared__ float sred8[8];
    __shared__ float sbm, sbinv;
    __shared__ float sav[4][64];
    int h = blockIdx.x;
    int t = threadIdx.x;
    if (t < 64) sq[t] = g_q0[h*HDIM + t];
    __syncthreads();

    // scores for row 0
    for (int j = t; j < NTOK; j += 256) {
        const float4* kp = (const float4*)(g_kv + (size_t)j*1024 + h*HDIM);
        float s = 0.f;
        #pragma unroll
        for (int d4 = 0; d4 < 16; d4++) {
            float4 k4 = kp[d4];
            const float* q4 = sq + (d4<<2);
            s = fmaf(q4[0], k4.x, s);
            s = fmaf(q4[1], k4.y, s);
            s = fmaf(q4[2], k4.z, s);
            s = fmaf(q4[3], k4.w, s);
        }
        float pos = g_angpos[j];         // row i=0
        int ip = (int)pos; float f = pos - (float)ip;
        const float* r0 = tab + (size_t)ip*8 + h;
        float bias = r0[0] + f*(r0[8] - r0[0]);
        sj[j] = fmaf(0.125f, s, bias);
    }
    __syncthreads();

    // block max
    float m = -1e30f;
    for (int j = t; j < NTOK; j += 256) m = fmaxf(m, sj[j]);
    #pragma unroll
    for (int o = 16; o > 0; o >>= 1)
        m = fmaxf(m, __shfl_xor_sync(0xffffffffu, m, o));
    if ((t & 31) == 0) sred8[t >> 5] = m;
    __syncthreads();
    if (t == 0) {
        float bm = sred8[0];
        #pragma unroll
        for (int q = 1; q < 8; q++) bm = fmaxf(bm, sred8[q]);
        sbm = bm;
    }
    __syncthreads();
    float bm = sbm;

    // exp in place + block sum
    float s = 0.f;
    for (int j = t; j < NTOK; j += 256) {
        float e = __expf(sj[j] - bm);
        sj[j] = e; s += e;
    }
    #pragma unroll
    for (int o = 16; o > 0; o >>= 1)
        s += __shfl_xor_sync(0xffffffffu, s, o);
    if ((t & 31) == 0) sred8[t >> 5] = s;
    __syncthreads();
    if (t == 0) {
        float bs = 0.f;
        #pragma unroll
        for (int q = 0; q < 8; q++) bs += sred8[q];
        sbinv = 1.f / bs;
    }
    __syncthreads();

    // AV: 64 d x 4 j-groups
    int d = t & 63, grp = t >> 6;
    float acc = 0.f;
    for (int j = grp; j < NTOK; j += 4)
        acc = fmaf(sj[j], g_kv[(size_t)j*1024 + 512 + h*HDIM + d], acc);
    sav[grp][d] = acc;
    __syncthreads();
    if (t < 64) {
        float o = (sav[0][t] + sav[1][t] + sav[2][t] + sav[3][t]) * sbinv;
        g_ao[h*HDIM + t] = o;            // row 0 only
    }
}

// ---------------- L2: proj + residual for row 0 ----------------
__global__ void __launch_bounds__(256) proj_row_kernel(
        const float* __restrict__ w, const float* __restrict__ b) {
    __shared__ float sa0[DIMM];
    int t = threadIdx.x;
    int n = blockIdx.x*256 + t;
    for (int c = t; c < DIMM; c += 256) sa0[c] = g_ao[c];
    __syncthreads();
    float acc = b[n] + g_h[n];
    #pragma unroll 8
    for (int c = 0; c < DIMM; c++)
        acc = fmaf(sa0[c], w[(size_t)c*DIMM + n], acc);
    g_h[n] = acc;
}

// ---------------- final: LN(row 0) -> fc2 -> out[2] ----------------
__global__ void final_kernel(const float* __restrict__ g, const float* __restrict__ b,
                             const float* __restrict__ w, const float* __restrict__ bias,
                             float* __restrict__ out) {
    int t = threadIdx.x;                  // 256 threads
    float v0 = g_h[t], v1 = g_h[t+256];
    float2 s = blockReduce2_256(v0+v1, v0*v0+v1*v1);
    float mean = s.x * (1.f/512.f);
    float inv  = rsqrtf(s.y*(1.f/512.f) - mean*mean + 1e-5f);
    float l0 = (v0-mean)*inv*g[t]     + b[t];
    float l1 = (v1-mean)*inv*g[t+256] + b[t+256];
    float p0 = l0*w[t*2]   + l1*w[(t+256)*2];
    float p1 = l0*w[t*2+1] + l1*w[(t+256)*2+1];
    float2 sp = blockReduce2_256(p0, p1);
    if (t == 0) { out[0] = sp.x + bias[0]; out[1] = sp.y + bias[1]; }
}

// ---------------- launch ----------------
extern "C" void kernel_launch(void* const* d_in, const int* in_sizes, int n_in,
                              void* d_out, int out_size) {
    const float* h_in   = (const float*)d_in[0];
    const float* coords = (const float*)d_in[1];
    const float* fc1_w  = (const float*)d_in[2];
    const float* fc1_b  = (const float*)d_in[3];
    const float* cls    = (const float*)d_in[4];
    const float* norm_g = (const float*)d_in[25];
    const float* norm_b = (const float*)d_in[26];
    const float* fc2_w  = (const float*)d_in[27];
    const float* fc2_b  = (const float*)d_in[28];
    const float* l1_ln_g = (const float*)d_in[5];
    const float* l1_ln_b = (const float*)d_in[6];
    const float* l1_qkv_w = (const float*)d_in[11];
    const float* l1_qkv_b = (const float*)d_in[12];
    const float* l1_proj_w = (const float*)d_in[13];
    const float* l1_proj_b = (const float*)d_in[14];
    const float* l2_ln_g = (const float*)d_in[15];
    const float* l2_ln_b = (const float*)d_in[16];
    const float* l2_qkv_w = (const float*)d_in[21];
    const float* l2_qkv_b = (const float*)d_in[22];
    const float* l2_proj_w = (const float*)d_in[23];
    const float* l2_proj_b = (const float*)d_in[24];

    float *p_h, *p_ln, *p_qkv, *p_kv, *p_ao, *p_part, *p_tab[2];
    cudaGetSymbolAddress((void**)&p_h,      g_h);
    cudaGetSymbolAddress((void**)&p_ln,     g_ln);
    cudaGetSymbolAddress((void**)&p_qkv,    g_qkv);
    cudaGetSymbolAddress((void**)&p_kv,     g_kv);
    cudaGetSymbolAddress((void**)&p_ao,     g_ao);
    cudaGetSymbolAddress((void**)&p_part,   g_part);
    cudaGetSymbolAddress((void**)&p_tab[0], g_table0);
    cudaGetSymbolAddress((void**)&p_tab[1], g_table1);

    angpos_kernel<<<(NPAIR + 255)/256, 256>>>(coords);
    cpb_table_kernel<<<dim3((TABN + 3 + 31)/32, 2), 256>>>(
        (const float*)d_in[7],  (const float*)d_in[8],
        (const float*)d_in[9],  (const float*)d_in[10], p_tab[0],
        (const float*)d_in[17], (const float*)d_in[18],
        (const float*)d_in[19], (const float*)d_in[20], p_tab[1]);

    // fc1: split-K x8 (K=1024 -> 8x128); fused reduce+relu+CLS+LN(L1)
    gemm_kernel<<<dim3(DIMM/64, (NPT+31)/32, 8), 128>>>(
        h_in, 1024, fc1_w, DIMM, (const float*)0,
        p_part, DIMM, NPT, DIMM, 128, FLAG_RAW);
    reduce_ln_kernel<<<NTOK, 256>>>(
        p_part, fc1_b, cls, p_h, p_ln, l1_ln_g, l1_ln_b, 8, 0);

    // ---- layer 1 (full) ----
    gemm_kernel<<<dim3(QKV3/64, (NTOK+31)/32, 2), 128>>>(
        p_ln, DIMM, l1_qkv_w, QKV3, (const float*)0,
        p_part, QKV3, NTOK, QKV3, 256, FLAG_RAW);
    reduce_kernel<<<(NTOK*QKV3/4 + 255)/256, 256>>>(
        p_part, l1_qkv_b, p_qkv, NTOK*QKV3, QKV3, 2, 0);
    scores_kernel<<<dim3(7, 13, NHEAD), 128>>>(p_tab[0]);
    softav_kernel<<<dim3(26, NHEAD), 256>>>();
    gemm_kernel<<<dim3(DIMM/64, (NTOK+31)/32, 4), 128>>>(
        p_ao, DIMM, l1_proj_w, DIMM, (const float*)0,
        p_part, DIMM, NTOK, DIMM, 128, FLAG_RAW);
    reduce_ln_kernel<<<NTOK, 256>>>(
        p_part, l1_proj_b, cls, p_h, p_ln, l2_ln_g, l2_ln_b, 4, 1);

    // ---- layer 2 (CLS row only downstream) ----
    // K,V for all tokens: N=1024 slice of qkv weights, split-K x2
    gemm_kernel<<<dim3(1024/64, (NTOK+31)/32, 2), 128>>>(
        p_ln, DIMM, l2_qkv_w + DIMM, QKV3, (const float*)0,
        p_part, 1024, NTOK, 1024, 256, FLAG_RAW);
    reduce_kernel<<<(NTOK*1024/4 + 255)/256, 256>>>(
        p_part, l2_qkv_b + DIMM, p_kv, NTOK*1024, 1024, 2, 0);
    q0_kernel<<<2, 256>>>(l2_qkv_w, l2_qkv_b);
    attn_row_kernel<<<NHEAD, 256>>>(p_tab[1]);
    proj_row_kernel<<<2, 256>>>(l2_proj_w, l2_proj_b);

    final_kernel<<<1, 256>>>(norm_g, norm_b, fc2_w, fc2_b, (float*)d_out);
}

// round 16
// speedup vs baseline: 1.3963x; 1.1154x over previous
#include <cuda_runtime.h>
#include <math.h>

#define NTOK 401
#define NPT  400
#define DIMM 512
#define NHEAD 8
#define HDIM 64
#define QKV3 1536
#define CPBH 512
#define NPAIR (NTOK*NTOK)
#define TABN 4096
#define PI_F 3.14159265358979323846f
#define FLAG_RELU 1
#define FLAG_ADD  2
#define FLAG_RAW  4

// ---------------- scratch (alloc-free, __device__ globals) ----------------
__device__ float  g_h[NTOK*DIMM];          // residual stream
__device__ float  g_ln[NTOK*DIMM];         // layernorm output
__device__ float  g_qkv[NTOK*QKV3];        // fused qkv (layer 1)
__device__ float  g_attn[NHEAD*NTOK*NTOK]; // attention logits (L1, 5.1 MB)
__device__ float  g_ao[NTOK*DIMM];         // attention output (pre-proj)
__device__ float  g_part[8*NTOK*DIMM];     // split-K partials (6.6 MB)
__device__ float  g_angpos[NPAIR];         // table position per pair (both layers)
__device__ float  g_table0[(TABN+4)*8];    // layer-1 bias table
__device__ float  g_table1[(TABN+4)*8];    // layer-2 bias table

// ---------------- small helpers ----------------
__device__ __forceinline__ float2 blockReduce2_256(float a, float b) {
    __shared__ float sa[8], sb[8];
    __syncthreads();
    #pragma unroll
    for (int o = 16; o > 0; o >>= 1) {
        a += __shfl_xor_sync(0xffffffffu, a, o);
        b += __shfl_xor_sync(0xffffffffu, b, o);
    }
    int w = threadIdx.x >> 5;
    if ((threadIdx.x & 31) == 0) { sa[w] = a; sb[w] = b; }
    __syncthreads();
    a = sa[0]+sa[1]+sa[2]+sa[3]+sa[4]+sa[5]+sa[6]+sa[7];
    b = sb[0]+sb[1]+sb[2]+sb[3]+sb[4]+sb[5]+sb[6]+sb[7];
    return make_float2(a, b);
}

// ---------------- prep: CPB tables (both layers) + angle positions --------
// blockIdx.x in [0,258): cpb table chunks (129 per layer).
// blockIdx.x in [258,887): angle positions (symmetry: compute i<j, derive j>i).
__global__ void __launch_bounds__(256) prep_kernel(
        const float* __restrict__ w1a, const float* __restrict__ b1a,
        const float* __restrict__ w2a, const float* __restrict__ b2a,
        float* __restrict__ outa,
        const float* __restrict__ w1b, const float* __restrict__ b1b,
        const float* __restrict__ w2b, const float* __restrict__ b2b,
        float* __restrict__ outb,
        const float* __restrict__ coords) {
    int bx = blockIdx.x;
    int t = threadIdx.x;
    if (bx >= 258) {
        int p = (bx - 258)*256 + t;
        if (p >= NPAIR) return;
        int i = p / NTOK, j = p - i*NTOK;
        if (i > j) return;
        if (i == j) { g_angpos[p] = (float)(TABN + 1); return; }
        float xi = (i == 0) ? 0.f : coords[2*(i-1)];
        float yi = (i == 0) ? 0.f : coords[2*(i-1)+1];
        float xj = coords[2*(j-1)];
        float yj = coords[2*(j-1)+1];
        float th = atan2f(yi - yj, xi - xj);
        float pos = (th + PI_F) * ((float)TABN / (2.0f*PI_F));
        pos = fminf(fmaxf(pos, 0.f), (float)TABN);
        g_angpos[p] = pos;
        float pos2 = pos + ((pos < (float)(TABN/2)) ? (float)(TABN/2) : -(float)(TABN/2));
        g_angpos[(size_t)j*NTOK + i] = pos2;
        return;
    }

    int layer = bx / 129;
    int cb    = bx % 129;
    const float* w1 = layer ? w1b : w1a;
    const float* b1 = layer ? b1b : b1a;
    const float* w2 = layer ? w2b : w2a;
    const float* b2 = layer ? b2b : b2a;
    float*      out = layer ? outb : outa;

    __shared__ float swx[CPBH], swy[CPBH], sbb[CPBH];
    __shared__ __align__(16) float sw2[CPBH*8];
    __shared__ float sred[8][32][9];
    for (int c = t; c < CPBH; c += 256) {
        swx[c] = w1[c]; swy[c] = w1[CPBH + c]; sbb[c] = b1[c];
    }
    for (int c = t; c < CPBH*2; c += 256)
        *(float4*)(sw2 + c*4) = *(const float4*)(w2 + c*4);
    __syncthreads();

    int e = t & 31;
    int w = t >> 5;
    int idx = cb*32 + e;
    float ux = 0.f, uy = 0.f;
    if (idx <= TABN) {
        float th = -PI_F + (2.0f*PI_F) * ((float)idx / (float)TABN);
        sincosf(th, &uy, &ux);
    }
    float acc[8] = {0.f,0.f,0.f,0.f,0.f,0.f,0.f,0.f};
    int c0 = w << 6;
    #pragma unroll 8
    for (int cc = 0; cc < 64; cc++) {
        int c = c0 + cc;
        float hv = fmaf(ux, swx[c], fmaf(uy, swy[c], sbb[c]));
        hv = fmaxf(hv, 0.f);
        float4 wa = *(const float4*)(sw2 + (c<<3));
        float4 wb = *(const float4*)(sw2 + (c<<3) + 4);
        acc[0] = fmaf(hv, wa.x, acc[0]);
        acc[1] = fmaf(hv, wa.y, acc[1]);
        acc[2] = fmaf(hv, wa.z, acc[2]);
        acc[3] = fmaf(hv, wa.w, acc[3]);
        acc[4] = fmaf(hv, wb.x, acc[4]);
        acc[5] = fmaf(hv, wb.y, acc[5]);
        acc[6] = fmaf(hv, wb.z, acc[6]);
        acc[7] = fmaf(hv, wb.w, acc[7]);
    }
    #pragma unroll
    for (int k = 0; k < 8; k++) sred[w][e][k] = acc[k];
    __syncthreads();

    int re = t >> 3, rk = t & 7;
    float s = 0.f;
    #pragma unroll
    for (int ww = 0; ww < 8; ww++) s += sred[ww][re][rk];
    int ridx = cb*32 + re;
    if (ridx <= TABN + 2) {
        float v = (ridx == TABN + 2) ? 0.f : s + b2[rk];
        out[(size_t)ridx*8 + rk] = v;
    }
}

// ---------------- 32x64-tile fp32 GEMM, 128 threads, 4x4/thread -----------
__global__ void __launch_bounds__(128) gemm_kernel(
        const float* __restrict__ A, int lda,
        const float* __restrict__ B, int ldb,
        const float* __restrict__ bias,
        float* __restrict__ C, int ldc,
        int M, int N, int K, int flags) {
    __shared__ __align__(16) float As[2][16][36];
    __shared__ __align__(16) float Bs[2][16][68];
    int t  = threadIdx.x;
    int m0 = blockIdx.y << 5, n0 = blockIdx.x << 6;
    int zi = blockIdx.z;
    const float* Az = A + (size_t)zi*K;
    const float* Bz = B + (size_t)zi*K*ldb;
    float* Cz = C + (size_t)zi*M*ldc;
    int arow = t >> 2, acol = (t & 3) << 2;
    int brow = t >> 3, bcol = (t & 7) << 3;
    int tx = t & 15, ty = t >> 4;
    float acc[4][4] = {};

    bool aval = (m0 + arow) < M;
    const float* Aptr = Az + (size_t)(m0 + arow)*lda + acol;
    const float* Bptr = Bz + (size_t)brow*ldb + n0 + bcol;

    float4 ra  = aval ? *(const float4*)Aptr : make_float4(0.f,0.f,0.f,0.f);
    float4 rb0 = *(const float4*)Bptr;
    float4 rb1 = *(const float4*)(Bptr + 4);
    int buf = 0;
    As[0][acol  ][arow] = ra.x; As[0][acol+1][arow] = ra.y;
    As[0][acol+2][arow] = ra.z; As[0][acol+3][arow] = ra.w;
    *(float4*)&Bs[0][brow][bcol]   = rb0;
    *(float4*)&Bs[0][brow][bcol+4] = rb1;
    __syncthreads();

    for (int k0 = 16; ; k0 += 16) {
        bool more = (k0 < K);
        if (more) {
            ra  = aval ? *(const float4*)(Aptr + k0) : make_float4(0.f,0.f,0.f,0.f);
            rb0 = *(const float4*)(Bptr + (size_t)k0*ldb);
            rb1 = *(const float4*)(Bptr + (size_t)k0*ldb + 4);
        }
        #pragma unroll
        for (int k = 0; k < 16; k++) {
            float4 a = *(const float4*)&As[buf][k][ty<<2];
            float4 b = *(const float4*)&Bs[buf][k][tx<<2];
            acc[0][0] = fmaf(a.x, b.x, acc[0][0]);
            acc[0][1] = fmaf(a.x, b.y, acc[0][1]);
            acc[0][2] = fmaf(a.x, b.z, acc[0][2]);
            acc[0][3] = fmaf(a.x, b.w, acc[0][3]);
            acc[1][0] = fmaf(a.y, b.x, acc[1][0]);
            acc[1][1] = fmaf(a.y, b.y, acc[1][1]);
            acc[1][2] = fmaf(a.y, b.z, acc[1][2]);
            acc[1][3] = fmaf(a.y, b.w, acc[1][3]);
            acc[2][0] = fmaf(a.z, b.x, acc[2][0]);
            acc[2][1] = fmaf(a.z, b.y, acc[2][1]);
            acc[2][2] = fmaf(a.z, b.z, acc[2][2]);
            acc[2][3] = fmaf(a.z, b.w, acc[2][3]);
            acc[3][0] = fmaf(a.w, b.x, acc[3][0]);
            acc[3][1] = fmaf(a.w, b.y, acc[3][1]);
            acc[3][2] = fmaf(a.w, b.z, acc[3][2]);
            acc[3][3] = fmaf(a.w, b.w, acc[3][3]);
        }
        if (!more) break;
        buf ^= 1;
        As[buf][acol  ][arow] = ra.x; As[buf][acol+1][arow] = ra.y;
        As[buf][acol+2][arow] = ra.z; As[buf][acol+3][arow] = ra.w;
        *(float4*)&Bs[buf][brow][bcol]   = rb0;
        *(float4*)&Bs[buf][brow][bcol+4] = rb1;
        __syncthreads();
    }

    if (flags & FLAG_RAW) {
        #pragma unroll
        for (int i = 0; i < 4; i++) {
            int m = m0 + (ty<<2) + i;
            if (m >= M) break;
            *(float4*)(Cz + (size_t)m*ldc + n0 + (tx<<2)) =
                make_float4(acc[i][0], acc[i][1], acc[i][2], acc[i][3]);
        }
        return;
    }
    float4 bv = *(const float4*)(bias + n0 + (tx<<2));
    #pragma unroll
    for (int i = 0; i < 4; i++) {
        int m = m0 + (ty<<2) + i;
        if (m >= M) break;
        float4 v = make_float4(acc[i][0]+bv.x, acc[i][1]+bv.y,
                               acc[i][2]+bv.z, acc[i][3]+bv.w);
        if (flags & FLAG_RELU) {
            v.x = fmaxf(v.x,0.f); v.y = fmaxf(v.y,0.f);
            v.z = fmaxf(v.z,0.f); v.w = fmaxf(v.w,0.f);
        }
        float4* cp = (float4*)(C + (size_t)m*ldc + n0 + (tx<<2));
        if (flags & FLAG_ADD) {
            float4 o = *cp;
            v.x += o.x; v.y += o.y; v.z += o.z; v.w += o.w;
        }
        *cp = v;
    }
}

// ---------------- split-K reduce: C = op(sum_s part[s] + bias) ------------
__global__ void __launch_bounds__(256) reduce_kernel(
        const float* __restrict__ part, const float* __restrict__ bias,
        float* __restrict__ C, int MN, int N, int S, int flags) {
    int idx = (blockIdx.x*256 + threadIdx.x) << 2;
    if (idx >= MN) return;
    float4 v = *(const float4*)(part + idx);
    for (int s = 1; s < S; s++) {
        float4 p = *(const float4*)(part + (size_t)s*MN + idx);
        v.x += p.x; v.y += p.y; v.z += p.z; v.w += p.w;
    }
    float4 bv = *(const float4*)(bias + (idx % N));
    v.x += bv.x; v.y += bv.y; v.z += bv.z; v.w += bv.w;
    if (flags & FLAG_RELU) {
        v.x = fmaxf(v.x,0.f); v.y = fmaxf(v.y,0.f);
        v.z = fmaxf(v.z,0.f); v.w = fmaxf(v.w,0.f);
    }
    float4* cp = (float4*)(C + idx);
    if (flags & FLAG_ADD) {
        float4 o = *cp;
        v.x += o.x; v.y += o.y; v.z += o.z; v.w += o.w;
    }
    *cp = v;
}

// ---------------- fused split-K reduce + residual + LayerNorm -------------
__global__ void __launch_bounds__(256) reduce_ln_kernel(
        const float* __restrict__ part, const float* __restrict__ bias,
        const float* __restrict__ cls,
        float* __restrict__ h, float* __restrict__ ln_out,
        const float* __restrict__ g, const float* __restrict__ b,
        int S, int mode) {
    int row = blockIdx.x;          // 0..400
    int t = threadIdx.x;           // 256
    float v0, v1;
    if (mode == 0) {
        if (row == 0) {
            v0 = cls[t]; v1 = cls[t+256];
        } else {
            size_t base = (size_t)(row-1)*DIMM;
            size_t MN = (size_t)NPT*DIMM;
            v0 = 0.f; v1 = 0.f;
            for (int s = 0; s < S; s++) {
                v0 += part[(size_t)s*MN + base + t];
                v1 += part[(size_t)s*MN + base + t + 256];
            }
            v0 = fmaxf(v0 + bias[t],     0.f);
            v1 = fmaxf(v1 + bias[t+256], 0.f);
        }
        h[(size_t)row*DIMM + t]       = v0;
        h[(size_t)row*DIMM + t + 256] = v1;
    } else {
        size_t base = (size_t)row*DIMM;
        size_t MN = (size_t)NTOK*DIMM;
        v0 = 0.f; v1 = 0.f;
        for (int s = 0; s < S; s++) {
            v0 += part[(size_t)s*MN + base + t];
            v1 += part[(size_t)s*MN + base + t + 256];
        }
        v0 += bias[t]     + h[base + t];
        v1 += bias[t+256] + h[base + t + 256];
        h[base + t]       = v0;
        h[base + t + 256] = v1;
    }
    float2 sr = blockReduce2_256(v0+v1, v0*v0+v1*v1);
    float mean = sr.x * (1.f/512.f);
    float inv  = rsqrtf(sr.y*(1.f/512.f) - mean*mean + 1e-5f);
    ln_out[(size_t)row*DIMM + t]       = (v0-mean)*inv*g[t]     + b[t];
    ln_out[(size_t)row*DIMM + t + 256] = (v1-mean)*inv*g[t+256] + b[t+256];
}

// ---------------- QK^T scores + fused CPB bias (layer 1) ----------------
__global__ void __launch_bounds__(128) scores_kernel(const float* __restrict__ tab) {
    __shared__ __align__(16) float Qs[64][36];   // [d][i]
    __shared__ __align__(16) float Ks[64][68];   // [d][j]
    int h  = blockIdx.z;
    int i0 = blockIdx.y << 5, j0 = blockIdx.x << 6;
    int t  = threadIdx.x;

    {
        int r = t >> 2, c = (t & 3) << 4;
        const float* qp = g_qkv + (size_t)(i0+r)*QKV3 + h*HDIM + c;
        bool v = (i0 + r) < NTOK;
        #pragma unroll
        for (int q = 0; q < 4; q++) {
            float4 x = v ? *(const float4*)(qp + (q<<2)) : make_float4(0.f,0.f,0.f,0.f);
            int d = c + (q<<2);
            Qs[d  ][r] = x.x; Qs[d+1][r] = x.y;
            Qs[d+2][r] = x.z; Qs[d+3][r] = x.w;
        }
    }
    {
        int r = t >> 1, c = (t & 1) << 5;
        const float* kp = g_qkv + (size_t)(j0+r)*QKV3 + DIMM + h*HDIM + c;
        bool v = (j0 + r) < NTOK;
        #pragma unroll
        for (int q = 0; q < 8; q++) {
            float4 x = v ? *(const float4*)(kp + (q<<2)) : make_float4(0.f,0.f,0.f,0.f);
            int d = c + (q<<2);
            Ks[d  ][r] = x.x; Ks[d+1][r] = x.y;
            Ks[d+2][r] = x.z; Ks[d+3][r] = x.w;
        }
    }
    __syncthreads();

    int tx = t & 15, ty = t >> 4;
    float acc[4][4] = {};
    #pragma unroll 8
    for (int d = 0; d < 64; d++) {
        float4 a = *(const float4*)&Qs[d][ty<<2];
        float4 b = *(const float4*)&Ks[d][tx<<2];
        acc[0][0] = fmaf(a.x, b.x, acc[0][0]);
        acc[0][1] = fmaf(a.x, b.y, acc[0][1]);
        acc[0][2] = fmaf(a.x, b.z, acc[0][2]);
        acc[0][3] = fmaf(a.x, b.w, acc[0][3]);
        acc[1][0] = fmaf(a.y, b.x, acc[1][0]);
        acc[1][1] = fmaf(a.y, b.y, acc[1][1]);
        acc[1][2] = fmaf(a.y, b.z, acc[1][2]);
        acc[1][3] = fmaf(a.y, b.w, acc[1][3]);
        acc[2][0] = fmaf(a.z, b.x, acc[2][0]);
        acc[2][1] = fmaf(a.z, b.y, acc[2][1]);
        acc[2][2] = fmaf(a.z, b.z, acc[2][2]);
        acc[2][3] = fmaf(a.z, b.w, acc[2][3]);
        acc[3][0] = fmaf(a.w, b.x, acc[3][0]);
        acc[3][1] = fmaf(a.w, b.y, acc[3][1]);
        acc[3][2] = fmaf(a.w, b.z, acc[3][2]);
        acc[3][3] = fmaf(a.w, b.w, acc[3][3]);
    }

    #pragma unroll
    for (int qi = 0; qi < 4; qi++) {
        int i = i0 + (ty<<2) + qi;
        if (i >= NTOK) break;
        #pragma unroll
        for (int qj = 0; qj < 4; qj++) {
            int j = j0 + (tx<<2) + qj;
            if (j < NTOK) {
                size_t p = (size_t)i*NTOK + j;
                float pos = g_angpos[p];
                int   ip  = (int)pos;
                float f   = pos - (float)ip;
                const float* r0 = tab + (size_t)ip*8 + h;
                float bias = r0[0] + f*(r0[8] - r0[0]);
                g_attn[(size_t)h*NTOK*NTOK + p] = fmaf(0.125f, acc[qi][qj], bias);
            }
        }
    }
}

// ---------------- fused softmax + attn@V (layer 1; 16 i-rows per CTA) -----
__global__ void __launch_bounds__(256) softav_kernel() {
    __shared__ float sa[16][33];
    __shared__ __align__(16) float sv[32][68];
    __shared__ float smx[16], sinv[16];
    int h  = blockIdx.y;
    int i0 = blockIdx.x << 4;
    int t  = threadIdx.x;

    {   // stats: 16 threads per row
        int row = t >> 4, k = t & 15;
        int gi  = i0 + row;
        int cgi = gi < NTOK ? gi : NTOK - 1;
        const float* arow = g_attn + ((size_t)h*NTOK + cgi)*NTOK;
        float m = -1e30f;
        for (int j = k; j < NTOK; j += 16) m = fmaxf(m, arow[j]);
        #pragma unroll
        for (int o = 1; o < 16; o <<= 1)
            m = fmaxf(m, __shfl_xor_sync(0xffffffffu, m, o));
        float s = 0.f;
        for (int j = k; j < NTOK; j += 16) s += __expf(arow[j] - m);
        #pragma unroll
        for (int o = 1; o < 16; o <<= 1)
            s += __shfl_xor_sync(0xffffffffu, s, o);
        if (k == 0) { smx[row] = m; sinv[row] = 1.f / s; }
    }
    __syncthreads();

    int tx = t & 15, ty = t >> 4;
    int d4 = tx << 2;
    int ar = t >> 4, ac = (t & 15) << 1;
    int vr = t >> 3, vc = (t & 7) << 3;
    float mrow = smx[ar];
    float acc[4] = {0.f, 0.f, 0.f, 0.f};
    for (int j0 = 0; j0 < NTOK; j0 += 32) {
        #pragma unroll
        for (int q = 0; q < 2; q++) {
            int i = i0 + ar, j = j0 + ac + q;
            float e = 0.f;
            if (i < NTOK && j < NTOK)
                e = __expf(g_attn[((size_t)h*NTOK + i)*NTOK + j] - mrow);
            sa[ar][ac+q] = e;
        }
        {
            const float* vp = g_qkv + (size_t)(j0+vr)*QKV3 + 2*DIMM + h*HDIM + vc;
            bool vi = (j0 + vr < NTOK);
            float4 z = make_float4(0.f,0.f,0.f,0.f);
            float4 v0 = vi ? *(const float4*)vp       : z;
            float4 v1 = vi ? *(const float4*)(vp + 4) : z;
            *(float4*)&sv[vr][vc]   = v0;
            *(float4*)&sv[vr][vc+4] = v1;
        }
        __syncthreads();
        #pragma unroll
        for (int j = 0; j < 32; j++) {
            float4 vv = *(const float4*)&sv[j][d4];
            float a0 = sa[ty][j];
            acc[0] = fmaf(a0, vv.x, acc[0]);
            acc[1] = fmaf(a0, vv.y, acc[1]);
            acc[2] = fmaf(a0, vv.z, acc[2]);
            acc[3] = fmaf(a0, vv.w, acc[3]);
        }
        __syncthreads();
    }
    int i = i0 + ty;
    if (i < NTOK) {
        float inv = sinv[ty];
        *(float4*)(g_ao + (size_t)i*DIMM + h*HDIM + d4) =
            make_float4(acc[0]*inv, acc[1]*inv, acc[2]*inv, acc[3]*inv);
    }
}

// ---------------- L2: attention row 0, fused q0 GEMV + kv-reduce ----------
// One CTA per head. K/V read as part0+part1+bias (kv gemm partials).
__global__ void __launch_bounds__(256) attn_row_kernel(
        const float* __restrict__ tab, const float* __restrict__ part,
        const float* __restrict__ qkv_w, const float* __restrict__ qkv_b) {
    __shared__ float sln0[DIMM];
    __shared__ float sq[64], skb[64], svb[64];
    __shared__ float sj[NTOK];
    __shared__ float sred8[8];
    __shared__ float sbm, sbinv;
    __shared__ float sav[4][64];
    int h = blockIdx.x;
    int t = threadIdx.x;
    size_t MN = (size_t)NTOK*1024;

    for (int c = t; c < DIMM; c += 256) sln0[c] = g_ln[c];
    if (t < 64) {
        skb[t] = qkv_b[DIMM   + h*HDIM + t];
        svb[t] = qkv_b[2*DIMM + h*HDIM + t];
    }
    __syncthreads();

    // q0 for this head: 64 outputs, 4-way c-split
    {
        int d = t & 63, qtr = t >> 6;
        float acc = 0.f;
        for (int c = qtr; c < DIMM; c += 4)
            acc = fmaf(sln0[c], qkv_w[(size_t)c*QKV3 + h*HDIM + d], acc);
        sav[qtr][d] = acc;
    }
    __syncthreads();
    if (t < 64)
        sq[t] = sav[0][t] + sav[1][t] + sav[2][t] + sav[3][t] + qkv_b[h*HDIM + t];
    __syncthreads();

    // scores for row 0 (K = part0 + part1 + bias)
    for (int j = t; j < NTOK; j += 256) {
        const float4* k0 = (const float4*)(part + (size_t)j*1024 + h*HDIM);
        const float4* k1 = (const float4*)(part + MN + (size_t)j*1024 + h*HDIM);
        float s = 0.f;
        #pragma unroll
        for (int d4 = 0; d4 < 16; d4++) {
            float4 a = k0[d4], b = k1[d4];
            const float* q4 = sq + (d4<<2);
            const float* b4 = skb + (d4<<2);
            s = fmaf(q4[0], a.x + b.x + b4[0], s);
            s = fmaf(q4[1], a.y + b.y + b4[1], s);
            s = fmaf(q4[2], a.z + b.z + b4[2], s);
            s = fmaf(q4[3], a.w + b.w + b4[3], s);
        }
        float pos = g_angpos[j];
        int ip = (int)pos; float f = pos - (float)ip;
        const float* r0 = tab + (size_t)ip*8 + h;
        float bias = r0[0] + f*(r0[8] - r0[0]);
        sj[j] = fmaf(0.125f, s, bias);
    }
    __syncthreads();

    // block max
    float m = -1e30f;
    for (int j = t; j < NTOK; j += 256) m = fmaxf(m, sj[j]);
    #pragma unroll
    for (int o = 16; o > 0; o >>= 1)
        m = fmaxf(m, __shfl_xor_sync(0xffffffffu, m, o));
    if ((t & 31) == 0) sred8[t >> 5] = m;
    __syncthreads();
    if (t == 0) {
        float bm = sred8[0];
        #pragma unroll
        for (int q = 1; q < 8; q++) bm = fmaxf(bm, sred8[q]);
        sbm = bm;
    }
    __syncthreads();
    float bm = sbm;

    float s = 0.f;
    for (int j = t; j < NTOK; j += 256) {
        float e = __expf(sj[j] - bm);
        sj[j] = e; s += e;
    }
    #pragma unroll
    for (int o = 16; o > 0; o >>= 1)
        s += __shfl_xor_sync(0xffffffffu, s, o);
    if ((t & 31) == 0) sred8[t >> 5] = s;
    __syncthreads();
    if (t == 0) {
        float bs = 0.f;
        #pragma unroll
        for (int q = 0; q < 8; q++) bs += sred8[q];
        sbinv = 1.f / bs;
    }
    __syncthreads();

    // AV (V = part0 + part1 + bias)
    {
        int d = t & 63, grp = t >> 6;
        float acc = 0.f;
        for (int j = grp; j < NTOK; j += 4) {
            float v = part[(size_t)j*1024 + 512 + h*HDIM + d]
                    + part[MN + (size_t)j*1024 + 512 + h*HDIM + d] + svb[d];
            acc = fmaf(sj[j], v, acc);
        }
        sav[grp][d] = acc;
    }
    __syncthreads();
    if (t < 64) {
        float o = (sav[0][t] + sav[1][t] + sav[2][t] + sav[3][t]) * sbinv;
        g_ao[h*HDIM + t] = o;
    }
}

// ---------------- L2: proj + residual for row 0 (8 CTAs x 64 outputs) -----
__global__ void __launch_bounds__(256) proj_row_kernel(
        const float* __restrict__ w, const float* __restrict__ b) {
    __shared__ float sa0[DIMM];
    __shared__ float sred[4][64];
    int t = threadIdx.x;
    int n0 = blockIdx.x << 6;
    for (int c = t; c < DIMM; c += 256) sa0[c] = g_ao[c];
    __syncthreads();
    int d = t & 63, qtr = t >> 6;
    float acc = 0.f;
    for (int c = qtr; c < DIMM; c += 4)
        acc = fmaf(sa0[c], w[(size_t)c*DIMM + n0 + d], acc);
    sred[qtr][d] = acc;
    __syncthreads();
    if (t < 64)
        g_h[n0+t] = sred[0][t] + sred[1][t] + sred[2][t] + sred[3][t]
                  + b[n0+t] + g_h[n0+t];
}

// ---------------- final: LN(row 0) -> fc2 -> out[2] ----------------
__global__ void final_kernel(const float* __restrict__ g, const float* __restrict__ b,
                             const float* __restrict__ w, const float* __restrict__ bias,
                             float* __restrict__ out) {
    int t = threadIdx.x;                  // 256 threads
    float v0 = g_h[t], v1 = g_h[t+256];
    float2 s = blockReduce2_256(v0+v1, v0*v0+v1*v1);
    float mean = s.x * (1.f/512.f);
    float inv  = rsqrtf(s.y*(1.f/512.f) - mean*mean + 1e-5f);
    float l0 = (v0-mean)*inv*g[t]     + b[t];
    float l1 = (v1-mean)*inv*g[t+256] + b[t+256];
    float p0 = l0*w[t*2]   + l1*w[(t+256)*2];
    float p1 = l0*w[t*2+1] + l1*w[(t+256)*2+1];
    float2 sp = blockReduce2_256(p0, p1);
    if (t == 0) { out[0] = sp.x + bias[0]; out[1] = sp.y + bias[1]; }
}

// ---------------- launch ----------------
extern "C" void kernel_launch(void* const* d_in, const int* in_sizes, int n_in,
                              void* d_out, int out_size) {
    const float* h_in   = (const float*)d_in[0];
    const float* coords = (const float*)d_in[1];
    const float* fc1_w  = (const float*)d_in[2];
    const float* fc1_b  = (const float*)d_in[3];
    const float* cls    = (const float*)d_in[4];
    const float* norm_g = (const float*)d_in[25];
    const float* norm_b = (const float*)d_in[26];
    const float* fc2_w  = (const float*)d_in[27];
    const float* fc2_b  = (const float*)d_in[28];
    const float* l1_ln_g = (const float*)d_in[5];
    const float* l1_ln_b = (const float*)d_in[6];
    const float* l1_qkv_w = (const float*)d_in[11];
    const float* l1_qkv_b = (const float*)d_in[12];
    const float* l1_proj_w = (const float*)d_in[13];
    const float* l1_proj_b = (const float*)d_in[14];
    const float* l2_ln_g = (const float*)d_in[15];
    const float* l2_ln_b = (const float*)d_in[16];
    const float* l2_qkv_w = (const float*)d_in[21];
    const float* l2_qkv_b = (const float*)d_in[22];
    const float* l2_proj_w = (const float*)d_in[23];
    const float* l2_proj_b = (const float*)d_in[24];

    float *p_h, *p_ln, *p_qkv, *p_ao, *p_part, *p_tab[2];
    cudaGetSymbolAddress((void**)&p_h,      g_h);
    cudaGetSymbolAddress((void**)&p_ln,     g_ln);
    cudaGetSymbolAddress((void**)&p_qkv,    g_qkv);
    cudaGetSymbolAddress((void**)&p_ao,     g_ao);
    cudaGetSymbolAddress((void**)&p_part,   g_part);
    cudaGetSymbolAddress((void**)&p_tab[0], g_table0);
    cudaGetSymbolAddress((void**)&p_tab[1], g_table1);

    // prep: CPB tables (both layers) + angle positions, one launch
    prep_kernel<<<258 + (NPAIR + 255)/256, 256>>>(
        (const float*)d_in[7],  (const float*)d_in[8],
        (const float*)d_in[9],  (const float*)d_in[10], p_tab[0],
        (const float*)d_in[17], (const float*)d_in[18],
        (const float*)d_in[19], (const float*)d_in[20], p_tab[1],
        coords);

    // fc1: split-K x8 (K=1024 -> 8x128); fused reduce+relu+CLS+LN(L1)
    gemm_kernel<<<dim3(DIMM/64, (NPT+31)/32, 8), 128>>>(
        h_in, 1024, fc1_w, DIMM, (const float*)0,
        p_part, DIMM, NPT, DIMM, 128, FLAG_RAW);
    reduce_ln_kernel<<<NTOK, 256>>>(
        p_part, fc1_b, cls, p_h, p_ln, l1_ln_g, l1_ln_b, 8, 0);

    // ---- layer 1 (full) ----
    gemm_kernel<<<dim3(QKV3/64, (NTOK+31)/32, 2), 128>>>(
        p_ln, DIMM, l1_qkv_w, QKV3, (const float*)0,
        p_part, QKV3, NTOK, QKV3, 256, FLAG_RAW);
    reduce_kernel<<<(NTOK*QKV3/4 + 255)/256, 256>>>(
        p_part, l1_qkv_b, p_qkv, NTOK*QKV3, QKV3, 2, 0);
    scores_kernel<<<dim3(7, 13, NHEAD), 128>>>(p_tab[0]);
    softav_kernel<<<dim3(26, NHEAD), 256>>>();
    gemm_kernel<<<dim3(DIMM/64, (NTOK+31)/32, 4), 128>>>(
        p_ao, DIMM, l1_proj_w, DIMM, (const float*)0,
        p_part, DIMM, NTOK, DIMM, 128, FLAG_RAW);
    reduce_ln_kernel<<<NTOK, 256>>>(
        p_part, l1_proj_b, cls, p_h, p_ln, l2_ln_g, l2_ln_b, 4, 1);

    // ---- layer 2 (CLS row only downstream) ----
    // K,V partials for all tokens: N=1024 slice of qkv weights, split-K x2
    gemm_kernel<<<dim3(1024/64, (NTOK+31)/32, 2), 128>>>(
        p_ln, DIMM, l2_qkv_w + DIMM, QKV3, (const float*)0,
        p_part, 1024, NTOK, 1024, 256, FLAG_RAW);
    // attention row 0: fused q0 GEMV + kv-reduce + softmax + AV
    attn_row_kernel<<<NHEAD, 256>>>(p_tab[1], p_part, l2_qkv_w, l2_qkv_b);
    proj_row_kernel<<<8, 256>>>(l2_proj_w, l2_proj_b);

    final_kernel<<<1, 256>>>(norm_g, norm_b, fc2_w, fc2_b, (float*)d_out);
}